// round 9
// baseline (speedup 1.0000x reference)
#include <cuda_runtime.h>
#include <cuda_bf16.h>
#include <cstdint>

#define Bb 2
#define Cc 256
#define Hh 48
#define Nn 110592        // 48*48*48
#define PLANE 2304       // 48*48
#define NH 4
#define DV 64
#define DQK 32
#define QKD 128
#define EPSILON 1e-6f

typedef unsigned long long ull;
typedef unsigned short ushort_t;

__device__ __forceinline__ void fma2(ull& d, ull a, ull b) {
    asm("fma.rn.f32x2 %0, %1, %2, %0;" : "+l"(d) : "l"(a), "l"(b));
}
__device__ __forceinline__ ull pack2(float lo, float hi) {
    ull r; asm("mov.b64 %0, {%1, %2};" : "=l"(r) : "f"(lo), "f"(hi)); return r;
}
__device__ __forceinline__ float2 unpack2(ull v) {
    float lo, hi; asm("mov.b64 {%0, %1}, %2;" : "=f"(lo), "=f"(hi) : "l"(v));
    return make_float2(lo, hi);
}
union F4U2 { float4 f4; ull u2[2]; };

// -------- scratch --------
__device__ __align__(16) float g_qk[(size_t)Bb * Cc * Nn];
__device__ __align__(16) float g_v[(size_t)Bb * Cc * Nn];
__device__ float g_kv[Bb * NH * DQK * DV];
__device__ float g_s[Bb * NH * DQK];
__device__ float g_kvn[Bb * NH * DQK * DV];

__device__ __forceinline__ uint32_t smem_u32(const void* p) {
    uint32_t a;
    asm("{ .reg .u64 t; cvta.to.shared.u64 t, %1; cvt.u32.u64 %0, t; }" : "=r"(a) : "l"(p));
    return a;
}

// ===================== mma.sync helpers (sm_80+ baseline PTX) ==============
__device__ __forceinline__ void ldsm4(uint32_t* r, uint32_t addr) {
    asm volatile("ldmatrix.sync.aligned.m8n8.x4.shared.b16 {%0,%1,%2,%3}, [%4];"
                 : "=r"(r[0]), "=r"(r[1]), "=r"(r[2]), "=r"(r[3]) : "r"(addr));
}
__device__ __forceinline__ void ldsm2t(uint32_t* r, uint32_t addr) {
    asm volatile("ldmatrix.sync.aligned.m8n8.x2.trans.shared.b16 {%0,%1}, [%2];"
                 : "=r"(r[0]), "=r"(r[1]) : "r"(addr));
}
__device__ __forceinline__ void mma_bf16(float* d, const uint32_t* a, const uint32_t* b) {
    asm volatile(
        "mma.sync.aligned.m16n8k16.row.col.f32.bf16.bf16.f32 "
        "{%0,%1,%2,%3}, {%4,%5,%6,%7}, {%8,%9}, {%0,%1,%2,%3};"
        : "+f"(d[0]), "+f"(d[1]), "+f"(d[2]), "+f"(d[3])
        : "r"(a[0]), "r"(a[1]), "r"(a[2]), "r"(a[3]), "r"(b[0]), "r"(b[1]));
}
__device__ __forceinline__ void cvt_hl4(float4 f, uint2& hi, uint2& lo) {
    __nv_bfloat16 hx = __float2bfloat16(f.x), hy = __float2bfloat16(f.y);
    __nv_bfloat16 hz = __float2bfloat16(f.z), hw = __float2bfloat16(f.w);
    __nv_bfloat16 lx = __float2bfloat16(f.x - __bfloat162float(hx));
    __nv_bfloat16 ly = __float2bfloat16(f.y - __bfloat162float(hy));
    __nv_bfloat16 lz = __float2bfloat16(f.z - __bfloat162float(hz));
    __nv_bfloat16 lw = __float2bfloat16(f.w - __bfloat162float(hw));
    hi.x = ((uint32_t)__bfloat16_as_ushort(hy) << 16) | __bfloat16_as_ushort(hx);
    hi.y = ((uint32_t)__bfloat16_as_ushort(hw) << 16) | __bfloat16_as_ushort(hz);
    lo.x = ((uint32_t)__bfloat16_as_ushort(ly) << 16) | __bfloat16_as_ushort(lx);
    lo.y = ((uint32_t)__bfloat16_as_ushort(lw) << 16) | __bfloat16_as_ushort(lz);
}
__device__ __forceinline__ void cvt_hl1(float f, ushort_t& h, ushort_t& l) {
    __nv_bfloat16 hb = __float2bfloat16(f);
    __nv_bfloat16 lb = __float2bfloat16(f - __bfloat162float(hb));
    h = __bfloat16_as_ushort(hb);
    l = __bfloat16_as_ushort(lb);
}

// ======================= K1: qk GEMM via mma.sync 3xBF16 ===================
#define GSM_AL 18432
#define GSM_BH 36864
#define GSM_BL 54272
#define GSM_TOT 71680

__global__ void __launch_bounds__(256, 2) k_gemm_mma(const float* __restrict__ x,
                                                     const float* __restrict__ Wq,
                                                     const float* __restrict__ Wk) {
    extern __shared__ __align__(16) char sm[];
    const int tid = threadIdx.x;
    const int lane = tid & 31, w = tid >> 5;
    const int n0 = blockIdx.x * 128;
    const int mh = blockIdx.y;
    const int b  = blockIdx.z;
    const float* Wsrc = mh ? Wk : Wq;
    const float* xb = x + (size_t)b * Cc * Nn;
    const uint32_t smb = smem_u32(sm);

    const int wm = (w & 1) * 64;
    const int wn = (w >> 1) * 32;

    const uint32_t aHi = smb + (wm + (lane & 15)) * 144 + (lane >> 4) * 16;
    const uint32_t aLo = aHi + GSM_AL;
    const uint32_t bHi = smb + GSM_BH + (lane & 15) * 272 + wn * 2;
    const uint32_t bLo = bHi + (GSM_BL - GSM_BH);

    float d[4][4][4];
#pragma unroll
    for (int mt = 0; mt < 4; mt++)
#pragma unroll
        for (int nt = 0; nt < 4; nt++)
#pragma unroll
            for (int r = 0; r < 4; r++) d[mt][nt][r] = 0.f;

    for (int kc = 0; kc < 4; kc++) {
        __syncthreads();
#pragma unroll
        for (int u = 0; u < 8; u++) {
            int i = u * 256 + tid;
            int row = i >> 4, g = i & 15;
            float4 f = *(const float4*)(Wsrc + (size_t)row * Cc + kc * 64 + g * 4);
            uint2 hi, lo; cvt_hl4(f, hi, lo);
            *(uint2*)(sm + row * 144 + g * 8) = hi;
            *(uint2*)(sm + GSM_AL + row * 144 + g * 8) = lo;
        }
#pragma unroll
        for (int u = 0; u < 8; u++) {
            int i = u * 256 + tid;
            int kr = i >> 5, ng = i & 31;
            float4 f = *(const float4*)(xb + (size_t)(kc * 64 + kr) * Nn + n0 + ng * 4);
            uint2 hi, lo; cvt_hl4(f, hi, lo);
            *(uint2*)(sm + GSM_BH + kr * 272 + ng * 8) = hi;
            *(uint2*)(sm + GSM_BL + kr * 272 + ng * 8) = lo;
        }
        __syncthreads();

#pragma unroll
        for (int s4 = 0; s4 < 4; s4++) {
            uint32_t ah[4][4], bh[4][2], t2[4][4];
#pragma unroll
            for (int mt = 0; mt < 4; mt++)
                ldsm4(ah[mt], aHi + mt * (16 * 144) + s4 * 32);
#pragma unroll
            for (int nt = 0; nt < 4; nt++)
                ldsm2t(bh[nt], bHi + s4 * (16 * 272) + nt * 16);
#pragma unroll
            for (int mt = 0; mt < 4; mt++)
#pragma unroll
                for (int nt = 0; nt < 4; nt++)
                    mma_bf16(d[mt][nt], ah[mt], bh[nt]);
#pragma unroll
            for (int nt = 0; nt < 4; nt++)
                ldsm2t(t2[nt], bLo + s4 * (16 * 272) + nt * 16);
#pragma unroll
            for (int mt = 0; mt < 4; mt++)
#pragma unroll
                for (int nt = 0; nt < 4; nt++)
                    mma_bf16(d[mt][nt], ah[mt], t2[nt]);
#pragma unroll
            for (int mt = 0; mt < 4; mt++)
                ldsm4(ah[mt], aLo + mt * (16 * 144) + s4 * 32);
#pragma unroll
            for (int mt = 0; mt < 4; mt++)
#pragma unroll
                for (int nt = 0; nt < 4; nt++)
                    mma_bf16(d[mt][nt], ah[mt], bh[nt]);
        }
    }

    float* outp = g_qk + (size_t)(b * Cc + mh * 128) * Nn + n0;
    const int r0 = lane >> 2, c0 = (lane & 3) * 2;
#pragma unroll
    for (int mt = 0; mt < 4; mt++) {
#pragma unroll
        for (int nt = 0; nt < 4; nt++) {
            float* p0 = outp + (size_t)(wm + mt * 16 + r0) * Nn + wn + nt * 8 + c0;
            *(float2*)p0 = make_float2(d[mt][nt][0], d[mt][nt][1]);
            float* p1 = p0 + (size_t)8 * Nn;
            *(float2*)p1 = make_float2(d[mt][nt][2], d[mt][nt][3]);
        }
    }
}

// ======================= K2: depthwise 3x3x3 conv (h-tiled rolling) ========
#define CONV_HT 12
__global__ __launch_bounds__(192) void k_conv_v(const float* __restrict__ x,
                                                const float* __restrict__ Wv,
                                                const float* __restrict__ bv) {
    __shared__ float xs[4][48][48];   // rolling window, slot = (plane+4)&3
    const int h0 = blockIdx.x * CONV_HT, c = blockIdx.y, b = blockIdx.z;
    const float* xc = x + ((size_t)b * Cc + c) * Nn;
    const int tid = threadIdx.x;

    auto loadp = [&](int p) {
        float* dst = (float*)xs[(p + 4) & 3];
        if (p >= 0 && p < Hh) {
            for (int i = tid; i < PLANE; i += 192) dst[i] = xc[(size_t)p * PLANE + i];
        } else {
            for (int i = tid; i < PLANE; i += 192) dst[i] = 0.f;
        }
    };

    float wv[27];
#pragma unroll
    for (int i = 0; i < 27; i++) wv[i] = Wv[c * 27 + i];
    const float bias = bv[c];

    loadp(h0 - 1); loadp(h0); loadp(h0 + 1);
    __syncthreads();

    const int w  = tid >> 2;
    const int d0 = (tid & 3) * 12;

    for (int hi = 0; hi < CONV_HT; hi++) {
        const int h = h0 + hi;
        float o[12];
#pragma unroll
        for (int j = 0; j < 12; j++) o[j] = bias;

#pragma unroll
        for (int hh = 0; hh < 3; hh++) {
            const float* plane = (const float*)xs[(h - 1 + hh + 4) & 3];
#pragma unroll
            for (int ww = 0; ww < 3; ww++) {
                int wg = w + ww - 1;
                if (wg < 0 || wg >= 48) continue;
                const float* row = plane + wg * 48;
                const float w0 = wv[(hh * 3 + ww) * 3 + 0];
                const float w1 = wv[(hh * 3 + ww) * 3 + 1];
                const float w2 = wv[(hh * 3 + ww) * 3 + 2];
                float xm = (d0 > 0) ? row[d0 - 1] : 0.f;
                float x0 = row[d0];
#pragma unroll
                for (int j = 0; j < 12; j++) {
                    int d = d0 + j;
                    float xp = (d + 1 < 48) ? row[d + 1] : 0.f;
                    o[j] += w0 * xm + w1 * x0 + w2 * xp;
                    xm = x0; x0 = xp;
                }
            }
        }

        float* vp = g_v + ((size_t)b * Cc + c) * Nn + (size_t)h * PLANE + w * 48 + d0;
#pragma unroll
        for (int q = 0; q < 3; q++)
            *(float4*)(vp + q * 4) = make_float4(o[q*4], o[q*4+1], o[q*4+2], o[q*4+3]);

        if (hi < CONV_HT - 1) loadp(h + 2);
        __syncthreads();
    }
}

// ======================= zero accumulators ===========================
__global__ void k_zero() {
    int i = blockIdx.x * 256 + threadIdx.x;
    if (i < Bb * NH * DQK * DV) g_kv[i] = 0.f;
    if (i < Bb * NH * DQK) g_s[i] = 0.f;
}

// ======================= K3: kv reduction via mma.sync =====================
// kv^T[dv][dk] = sum_n V[dv][n]*exp(K[dk][n]); s[dk] = sum_n exp(K[dk][n])
// Block processes KV_NT n in NCHUNK chunks of 256; accumulators persist.
#define KV_NT 2048
#define NCHUNK 8
#define E_STR 80      // 32 dk * 2B + 16 pad; 16B-aligned; bank step 20 -> conflict-free
#define V_STR 528     // 256 n * 2B + 16 pad; 16B-aligned; bank step 4  -> conflict-free
#define KSM_EH 0
#define KSM_EL 20480
#define KSM_VH 40960
#define KSM_VL 74752
#define KSM_TOT 108544

__global__ __launch_bounds__(256) void k_kv_mma() {
    extern __shared__ __align__(16) char km[];
    const int b = blockIdx.z, head = blockIdx.y;
    const int n0 = blockIdx.x * KV_NT;
    const float* kp = g_qk + ((size_t)b * Cc + QKD + head * DQK) * Nn + n0;
    const float* vp = g_v  + ((size_t)b * Cc + head * DV) * Nn + n0;
    const int tid = threadIdx.x, lane = tid & 31, w = tid >> 5;
    const uint32_t smb = smem_u32(km);

    float d[16][4];
#pragma unroll
    for (int f = 0; f < 16; f++)
#pragma unroll
        for (int r = 0; r < 4; r++) d[f][r] = 0.f;
    float s_acc = 0.f;

    const int dk = tid >> 3, q0 = tid & 7;          // E staging role
    const int dvr = tid >> 2, vq0 = tid & 3;        // V staging role

    const uint32_t aH = smb + KSM_VH + (lane & 15) * V_STR + (lane >> 4) * 16;
    const uint32_t aL = aH + (KSM_VL - KSM_VH);
    const uint32_t bH = smb + KSM_EH + (lane & 15) * E_STR;
    const uint32_t bL = bH + (KSM_EL - KSM_EH);

    for (int ch = 0; ch < NCHUNK; ch++) {
        const int cb = ch * 256;
        __syncthreads();   // prior chunk's mma reads done before overwrite

        // ---- stage E^T = exp(K) [n][dk] bf16 hi/lo; accumulate s ----
        {
            const float* krow = kp + (size_t)dk * Nn + cb;
#pragma unroll
            for (int u = 0; u < 8; u++) {
                int col = (q0 + u * 8) * 4;
                float4 f = *(const float4*)(krow + col);
                f.x = __expf(f.x); f.y = __expf(f.y); f.z = __expf(f.z); f.w = __expf(f.w);
                s_acc += f.x + f.y + f.z + f.w;
                ushort_t h, l;
                cvt_hl1(f.x, h, l);
                *(ushort_t*)(km + KSM_EH + (size_t)(col + 0) * E_STR + dk * 2) = h;
                *(ushort_t*)(km + KSM_EL + (size_t)(col + 0) * E_STR + dk * 2) = l;
                cvt_hl1(f.y, h, l);
                *(ushort_t*)(km + KSM_EH + (size_t)(col + 1) * E_STR + dk * 2) = h;
                *(ushort_t*)(km + KSM_EL + (size_t)(col + 1) * E_STR + dk * 2) = l;
                cvt_hl1(f.z, h, l);
                *(ushort_t*)(km + KSM_EH + (size_t)(col + 2) * E_STR + dk * 2) = h;
                *(ushort_t*)(km + KSM_EL + (size_t)(col + 2) * E_STR + dk * 2) = l;
                cvt_hl1(f.w, h, l);
                *(ushort_t*)(km + KSM_EH + (size_t)(col + 3) * E_STR + dk * 2) = h;
                *(ushort_t*)(km + KSM_EL + (size_t)(col + 3) * E_STR + dk * 2) = l;
            }
        }
        // ---- stage V [dv][n] bf16 hi/lo ----
        {
            const float* vrow = vp + (size_t)dvr * Nn + cb;
#pragma unroll
            for (int u = 0; u < 16; u++) {
                int quad = vq0 + u * 4;
                float4 f = *(const float4*)(vrow + quad * 4);
                uint2 hi, lo; cvt_hl4(f, hi, lo);
                *(uint2*)(km + KSM_VH + (size_t)dvr * V_STR + quad * 8) = hi;
                *(uint2*)(km + KSM_VL + (size_t)dvr * V_STR + quad * 8) = lo;
            }
        }
        __syncthreads();

        // ---- mma: warp w handles k16 steps {2w, 2w+1} of this chunk ----
#pragma unroll
        for (int ss = 0; ss < 2; ss++) {
            const int s = w * 2 + ss;
            uint32_t av[4][4], be[4][2], bl[4][2];
#pragma unroll
            for (int mt = 0; mt < 4; mt++)
                ldsm4(av[mt], aH + mt * (16 * V_STR) + s * 32);
#pragma unroll
            for (int nt = 0; nt < 4; nt++)
                ldsm2t(be[nt], bH + s * (16 * E_STR) + nt * 16);
#pragma unroll
            for (int mt = 0; mt < 4; mt++)
#pragma unroll
                for (int nt = 0; nt < 4; nt++)
                    mma_bf16(d[mt * 4 + nt], av[mt], be[nt]);        // vh*eh
#pragma unroll
            for (int nt = 0; nt < 4; nt++)
                ldsm2t(bl[nt], bL + s * (16 * E_STR) + nt * 16);
#pragma unroll
            for (int mt = 0; mt < 4; mt++)
#pragma unroll
                for (int nt = 0; nt < 4; nt++)
                    mma_bf16(d[mt * 4 + nt], av[mt], bl[nt]);        // vh*el
#pragma unroll
            for (int mt = 0; mt < 4; mt++)
                ldsm4(av[mt], aL + mt * (16 * V_STR) + s * 32);
#pragma unroll
            for (int mt = 0; mt < 4; mt++)
#pragma unroll
                for (int nt = 0; nt < 4; nt++)
                    mma_bf16(d[mt * 4 + nt], av[mt], be[nt]);        // vl*eh
        }
    }

    // ---- s: reduce over the 8 threads sharing dk, one atomic each ----
#pragma unroll
    for (int o = 4; o; o >>= 1) s_acc += __shfl_down_sync(0xffffffffu, s_acc, o, 8);
    if (q0 == 0) atomicAdd(&g_s[(b * NH + head) * DQK + dk], s_acc);

    // ---- cross-warp reduce kv in smem, then one atomic set per block ----
    __syncthreads();
    float* red = (float*)km;
#pragma unroll
    for (int f = 0; f < 16; f++)
#pragma unroll
        for (int r = 0; r < 4; r++)
            red[w * 2048 + lane * 64 + f * 4 + r] = d[f][r];
    __syncthreads();

    float* kvp = g_kv + (size_t)((b * NH + head) * DQK) * DV;
#pragma unroll
    for (int j = 0; j < 8; j++) {
        const int e = j * 256 + tid;
        float ssum = 0.f;
#pragma unroll
        for (int ww = 0; ww < 8; ww++) ssum += red[ww * 2048 + e];
        const int l = e >> 6, idx = e & 63;
        const int f = idx >> 2, r = idx & 3;
        const int mt = f >> 2, nt = f & 3;
        const int dv = mt * 16 + (l >> 2) + ((r >> 1) << 3);
        const int dkk = nt * 8 + (l & 3) * 2 + (r & 1);
        atomicAdd(&kvp[dkk * DV + dv], ssum);
    }
}

// ======================= K4: normalize kv ===========================
__global__ void k_kvnorm() {
    int i = blockIdx.x * 256 + threadIdx.x;
    if (i < Bb * NH * DQK * DV)
        g_kvn[i] = g_kv[i] / g_s[i / DV];
}

// ======================= K5: q softmax + matvec -> out =============
__global__ __launch_bounds__(256) void k_final(float* __restrict__ out) {
    __shared__ __align__(16) float kvs[NH][DQK][DV];
    const int b = blockIdx.y;
    const int n = blockIdx.x * 256 + threadIdx.x;
    for (int i = threadIdx.x; i < NH * DQK * DV; i += 256)
        ((float*)kvs)[i] = g_kvn[b * NH * DQK * DV + i];
    __syncthreads();

    const float* qp = g_qk + (size_t)b * Cc * Nn;
    float* op = out + (size_t)b * Cc * Nn;
    const float inv1e = 1.f / (1.f + EPSILON);

#pragma unroll 1
    for (int head = 0; head < NH; head++) {
        float e[DQK];
        float ssum = 0.f;
#pragma unroll
        for (int dk = 0; dk < DQK; dk++) {
            e[dk] = __expf(qp[(size_t)(head * DQK + dk) * Nn + n]);
            ssum += e[dk];
        }
        const float scale = inv1e / ssum;
        ull e2[DQK];
#pragma unroll
        for (int dk = 0; dk < DQK; dk++) {
            float s = e[dk] * scale;
            e2[dk] = pack2(s, s);
        }
#pragma unroll 1
        for (int dvg = 0; dvg < 8; dvg++) {
            ull a2[4] = {0ull, 0ull, 0ull, 0ull};
#pragma unroll
            for (int dk = 0; dk < DQK; dk++) {
                F4U2 ka, kb;
                ka.f4 = *(float4*)&kvs[head][dk][dvg * 8];
                kb.f4 = *(float4*)&kvs[head][dk][dvg * 8 + 4];
                fma2(a2[0], e2[dk], ka.u2[0]);
                fma2(a2[1], e2[dk], ka.u2[1]);
                fma2(a2[2], e2[dk], kb.u2[0]);
                fma2(a2[3], e2[dk], kb.u2[1]);
            }
            const int c = head * DV + dvg * 8;
#pragma unroll
            for (int p = 0; p < 4; p++) {
                float2 r = unpack2(a2[p]);
                op[(size_t)(c + 2 * p)     * Nn + n] = r.x;
                op[(size_t)(c + 2 * p + 1) * Nn + n] = r.y;
            }
        }
    }
}

// ======================= launch ===========================
extern "C" void kernel_launch(void* const* d_in, const int* in_sizes, int n_in,
                              void* d_out, int out_size) {
    const float* x  = (const float*)d_in[0];
    const float* Wq = (const float*)d_in[1];
    const float* Wk = (const float*)d_in[2];
    const float* Wv = (const float*)d_in[3];
    const float* bv = (const float*)d_in[4];
    float* out = (float*)d_out;

    cudaFuncSetAttribute(k_gemm_mma, cudaFuncAttributeMaxDynamicSharedMemorySize, GSM_TOT);
    cudaFuncSetAttribute(k_kv_mma, cudaFuncAttributeMaxDynamicSharedMemorySize, KSM_TOT);

    k_gemm_mma<<<dim3(Nn / 128, 2, Bb), 256, GSM_TOT>>>(x, Wq, Wk);
    k_conv_v<<<dim3(Hh / CONV_HT, Cc, Bb), 192>>>(x, Wv, bv);
    k_zero<<<64, 256>>>();
    k_kv_mma<<<dim3(Nn / KV_NT, NH, Bb), 256, KSM_TOT>>>();
    k_kvnorm<<<64, 256>>>();
    k_final<<<dim3(Nn / 256, Bb), 256>>>(out);
}

// round 10
// speedup vs baseline: 1.1515x; 1.1515x over previous
#include <cuda_runtime.h>
#include <cuda_bf16.h>
#include <cstdint>

#define Bb 2
#define Cc 256
#define Hh 48
#define Nn 110592        // 48*48*48
#define PLANE 2304       // 48*48
#define NH 4
#define DV 64
#define DQK 32
#define QKD 128
#define EPSILON 1e-6f

typedef unsigned long long ull;
typedef unsigned short ushort_t;

__device__ __forceinline__ void fma2(ull& d, ull a, ull b) {
    asm("fma.rn.f32x2 %0, %1, %2, %0;" : "+l"(d) : "l"(a), "l"(b));
}
__device__ __forceinline__ ull pack2(float lo, float hi) {
    ull r; asm("mov.b64 %0, {%1, %2};" : "=l"(r) : "f"(lo), "f"(hi)); return r;
}
__device__ __forceinline__ float2 unpack2(ull v) {
    float lo, hi; asm("mov.b64 {%0, %1}, %2;" : "=f"(lo), "=f"(hi) : "l"(v));
    return make_float2(lo, hi);
}
union F4U2 { float4 f4; ull u2[2]; };

// -------- scratch --------
__device__ __align__(16) float g_qk[(size_t)Bb * Cc * Nn];
__device__ __align__(16) float g_v[(size_t)Bb * Cc * Nn];
__device__ float g_kv[Bb * NH * DQK * DV];
__device__ float g_s[Bb * NH * DQK];
__device__ float g_kvn[Bb * NH * DQK * DV];

__device__ __forceinline__ uint32_t smem_u32(const void* p) {
    uint32_t a;
    asm("{ .reg .u64 t; cvta.to.shared.u64 t, %1; cvt.u32.u64 %0, t; }" : "=r"(a) : "l"(p));
    return a;
}

// ===================== mma.sync helpers (sm_80+ baseline PTX) ==============
__device__ __forceinline__ void ldsm4(uint32_t* r, uint32_t addr) {
    asm volatile("ldmatrix.sync.aligned.m8n8.x4.shared.b16 {%0,%1,%2,%3}, [%4];"
                 : "=r"(r[0]), "=r"(r[1]), "=r"(r[2]), "=r"(r[3]) : "r"(addr));
}
__device__ __forceinline__ void ldsm2t(uint32_t* r, uint32_t addr) {
    asm volatile("ldmatrix.sync.aligned.m8n8.x2.trans.shared.b16 {%0,%1}, [%2];"
                 : "=r"(r[0]), "=r"(r[1]) : "r"(addr));
}
__device__ __forceinline__ void mma_bf16(float* d, const uint32_t* a, const uint32_t* b) {
    asm volatile(
        "mma.sync.aligned.m16n8k16.row.col.f32.bf16.bf16.f32 "
        "{%0,%1,%2,%3}, {%4,%5,%6,%7}, {%8,%9}, {%0,%1,%2,%3};"
        : "+f"(d[0]), "+f"(d[1]), "+f"(d[2]), "+f"(d[3])
        : "r"(a[0]), "r"(a[1]), "r"(a[2]), "r"(a[3]), "r"(b[0]), "r"(b[1]));
}
__device__ __forceinline__ void cvt_hl4(float4 f, uint2& hi, uint2& lo) {
    __nv_bfloat16 hx = __float2bfloat16(f.x), hy = __float2bfloat16(f.y);
    __nv_bfloat16 hz = __float2bfloat16(f.z), hw = __float2bfloat16(f.w);
    __nv_bfloat16 lx = __float2bfloat16(f.x - __bfloat162float(hx));
    __nv_bfloat16 ly = __float2bfloat16(f.y - __bfloat162float(hy));
    __nv_bfloat16 lz = __float2bfloat16(f.z - __bfloat162float(hz));
    __nv_bfloat16 lw = __float2bfloat16(f.w - __bfloat162float(hw));
    hi.x = ((uint32_t)__bfloat16_as_ushort(hy) << 16) | __bfloat16_as_ushort(hx);
    hi.y = ((uint32_t)__bfloat16_as_ushort(hw) << 16) | __bfloat16_as_ushort(hz);
    lo.x = ((uint32_t)__bfloat16_as_ushort(ly) << 16) | __bfloat16_as_ushort(lx);
    lo.y = ((uint32_t)__bfloat16_as_ushort(lw) << 16) | __bfloat16_as_ushort(lz);
}
// float2 -> packed bf16x2 hi and lo (element 0 in low half, per ldmatrix convention)
__device__ __forceinline__ void cvt_hl2(float2 f, uint32_t& h, uint32_t& l) {
    __nv_bfloat16 hx = __float2bfloat16(f.x), hy = __float2bfloat16(f.y);
    __nv_bfloat16 lx = __float2bfloat16(f.x - __bfloat162float(hx));
    __nv_bfloat16 ly = __float2bfloat16(f.y - __bfloat162float(hy));
    h = ((uint32_t)__bfloat16_as_ushort(hy) << 16) | __bfloat16_as_ushort(hx);
    l = ((uint32_t)__bfloat16_as_ushort(ly) << 16) | __bfloat16_as_ushort(lx);
}

// ======================= K1: qk GEMM via mma.sync 3xBF16 ===================
#define GSM_AL 18432
#define GSM_BH 36864
#define GSM_BL 54272
#define GSM_TOT 71680

__global__ void __launch_bounds__(256, 2) k_gemm_mma(const float* __restrict__ x,
                                                     const float* __restrict__ Wq,
                                                     const float* __restrict__ Wk) {
    extern __shared__ __align__(16) char sm[];
    const int tid = threadIdx.x;
    const int lane = tid & 31, w = tid >> 5;
    const int n0 = blockIdx.x * 128;
    const int mh = blockIdx.y;
    const int b  = blockIdx.z;
    const float* Wsrc = mh ? Wk : Wq;
    const float* xb = x + (size_t)b * Cc * Nn;
    const uint32_t smb = smem_u32(sm);

    const int wm = (w & 1) * 64;
    const int wn = (w >> 1) * 32;

    const uint32_t aHi = smb + (wm + (lane & 15)) * 144 + (lane >> 4) * 16;
    const uint32_t aLo = aHi + GSM_AL;
    const uint32_t bHi = smb + GSM_BH + (lane & 15) * 272 + wn * 2;
    const uint32_t bLo = bHi + (GSM_BL - GSM_BH);

    float d[4][4][4];
#pragma unroll
    for (int mt = 0; mt < 4; mt++)
#pragma unroll
        for (int nt = 0; nt < 4; nt++)
#pragma unroll
            for (int r = 0; r < 4; r++) d[mt][nt][r] = 0.f;

    for (int kc = 0; kc < 4; kc++) {
        __syncthreads();
#pragma unroll
        for (int u = 0; u < 8; u++) {
            int i = u * 256 + tid;
            int row = i >> 4, g = i & 15;
            float4 f = *(const float4*)(Wsrc + (size_t)row * Cc + kc * 64 + g * 4);
            uint2 hi, lo; cvt_hl4(f, hi, lo);
            *(uint2*)(sm + row * 144 + g * 8) = hi;
            *(uint2*)(sm + GSM_AL + row * 144 + g * 8) = lo;
        }
#pragma unroll
        for (int u = 0; u < 8; u++) {
            int i = u * 256 + tid;
            int kr = i >> 5, ng = i & 31;
            float4 f = *(const float4*)(xb + (size_t)(kc * 64 + kr) * Nn + n0 + ng * 4);
            uint2 hi, lo; cvt_hl4(f, hi, lo);
            *(uint2*)(sm + GSM_BH + kr * 272 + ng * 8) = hi;
            *(uint2*)(sm + GSM_BL + kr * 272 + ng * 8) = lo;
        }
        __syncthreads();

#pragma unroll
        for (int s4 = 0; s4 < 4; s4++) {
            uint32_t ah[4][4], bh[4][2], t2[4][4];
#pragma unroll
            for (int mt = 0; mt < 4; mt++)
                ldsm4(ah[mt], aHi + mt * (16 * 144) + s4 * 32);
#pragma unroll
            for (int nt = 0; nt < 4; nt++)
                ldsm2t(bh[nt], bHi + s4 * (16 * 272) + nt * 16);
#pragma unroll
            for (int mt = 0; mt < 4; mt++)
#pragma unroll
                for (int nt = 0; nt < 4; nt++)
                    mma_bf16(d[mt][nt], ah[mt], bh[nt]);
#pragma unroll
            for (int nt = 0; nt < 4; nt++)
                ldsm2t(t2[nt], bLo + s4 * (16 * 272) + nt * 16);
#pragma unroll
            for (int mt = 0; mt < 4; mt++)
#pragma unroll
                for (int nt = 0; nt < 4; nt++)
                    mma_bf16(d[mt][nt], ah[mt], t2[nt]);
#pragma unroll
            for (int mt = 0; mt < 4; mt++)
                ldsm4(ah[mt], aLo + mt * (16 * 144) + s4 * 32);
#pragma unroll
            for (int mt = 0; mt < 4; mt++)
#pragma unroll
                for (int nt = 0; nt < 4; nt++)
                    mma_bf16(d[mt][nt], ah[mt], bh[nt]);
        }
    }

    float* outp = g_qk + (size_t)(b * Cc + mh * 128) * Nn + n0;
    const int r0 = lane >> 2, c0 = (lane & 3) * 2;
#pragma unroll
    for (int mt = 0; mt < 4; mt++) {
#pragma unroll
        for (int nt = 0; nt < 4; nt++) {
            float* p0 = outp + (size_t)(wm + mt * 16 + r0) * Nn + wn + nt * 8 + c0;
            *(float2*)p0 = make_float2(d[mt][nt][0], d[mt][nt][1]);
            float* p1 = p0 + (size_t)8 * Nn;
            *(float2*)p1 = make_float2(d[mt][nt][2], d[mt][nt][3]);
        }
    }
}

// ======================= K2: depthwise 3x3x3 conv (h-tiled rolling) ========
#define CONV_HT 12
__global__ __launch_bounds__(192) void k_conv_v(const float* __restrict__ x,
                                                const float* __restrict__ Wv,
                                                const float* __restrict__ bv) {
    __shared__ float xs[4][48][48];   // rolling window, slot = (plane+4)&3
    const int h0 = blockIdx.x * CONV_HT, c = blockIdx.y, b = blockIdx.z;
    const float* xc = x + ((size_t)b * Cc + c) * Nn;
    const int tid = threadIdx.x;

    auto loadp = [&](int p) {
        float* dst = (float*)xs[(p + 4) & 3];
        if (p >= 0 && p < Hh) {
            for (int i = tid; i < PLANE; i += 192) dst[i] = xc[(size_t)p * PLANE + i];
        } else {
            for (int i = tid; i < PLANE; i += 192) dst[i] = 0.f;
        }
    };

    float wv[27];
#pragma unroll
    for (int i = 0; i < 27; i++) wv[i] = Wv[c * 27 + i];
    const float bias = bv[c];

    loadp(h0 - 1); loadp(h0); loadp(h0 + 1);
    __syncthreads();

    const int w  = tid >> 2;
    const int d0 = (tid & 3) * 12;

    for (int hi = 0; hi < CONV_HT; hi++) {
        const int h = h0 + hi;
        float o[12];
#pragma unroll
        for (int j = 0; j < 12; j++) o[j] = bias;

#pragma unroll
        for (int hh = 0; hh < 3; hh++) {
            const float* plane = (const float*)xs[(h - 1 + hh + 4) & 3];
#pragma unroll
            for (int ww = 0; ww < 3; ww++) {
                int wg = w + ww - 1;
                if (wg < 0 || wg >= 48) continue;
                const float* row = plane + wg * 48;
                const float w0 = wv[(hh * 3 + ww) * 3 + 0];
                const float w1 = wv[(hh * 3 + ww) * 3 + 1];
                const float w2 = wv[(hh * 3 + ww) * 3 + 2];
                float xm = (d0 > 0) ? row[d0 - 1] : 0.f;
                float x0 = row[d0];
#pragma unroll
                for (int j = 0; j < 12; j++) {
                    int d = d0 + j;
                    float xp = (d + 1 < 48) ? row[d + 1] : 0.f;
                    o[j] += w0 * xm + w1 * x0 + w2 * xp;
                    xm = x0; x0 = xp;
                }
            }
        }

        float* vp = g_v + ((size_t)b * Cc + c) * Nn + (size_t)h * PLANE + w * 48 + d0;
#pragma unroll
        for (int q = 0; q < 3; q++)
            *(float4*)(vp + q * 4) = make_float4(o[q*4], o[q*4+1], o[q*4+2], o[q*4+3]);

        if (hi < CONV_HT - 1) loadp(h + 2);
        __syncthreads();
    }
}

// ======================= zero accumulators ===========================
__global__ void k_zero() {
    int i = blockIdx.x * 256 + threadIdx.x;
    if (i < Bb * NH * DQK * DV) g_kv[i] = 0.f;
    if (i < Bb * NH * DQK) g_s[i] = 0.f;
}

// ======================= K3: kv reduction, smem-free direct-fragment mma ===
// kv[dk][dv] = sum_n exp(K[dk][n]) * V[dv][n];  s[dk] = sum_n exp(K[dk][n])
// A = E (m=dk, k=n, row-major natural), B = V (n-dim=dv, k=n, B^T row-major
// natural) -> fragments assembled in registers straight from global. No
// mainloop smem/barriers. smem (64KB) used only for the final warp-reduce.
#define KVB 4096     // n per block -> grid.x = 27

__global__ __launch_bounds__(256) void k_kv_mma() {
    extern __shared__ __align__(16) float red[];   // 8 warps * 2048 floats
    const int b = blockIdx.z, head = blockIdx.y;
    const int n0 = blockIdx.x * KVB;
    const float* kp = g_qk + ((size_t)b * Cc + QKD + head * DQK) * Nn + n0;
    const float* vp = g_v  + ((size_t)b * Cc + head * DV) * Nn + n0;
    const int tid = threadIdx.x, lane = tid & 31, w = tid >> 5;
    const int r = lane >> 2, kp2 = (lane & 3) * 2;

    // E row pointers: mt0 -> rows r, r+8; mt1 -> rows r+16, r+24
    const float* eR[4] = {
        kp + (size_t)(r)      * Nn, kp + (size_t)(r + 8)  * Nn,
        kp + (size_t)(r + 16) * Nn, kp + (size_t)(r + 24) * Nn };
    const float* vR[8];
#pragma unroll
    for (int nt = 0; nt < 8; nt++) vR[nt] = vp + (size_t)(nt * 8 + r) * Nn;

    float d[2][8][4];
#pragma unroll
    for (int mt = 0; mt < 2; mt++)
#pragma unroll
        for (int nt = 0; nt < 8; nt++)
#pragma unroll
            for (int q = 0; q < 4; q++) d[mt][nt][q] = 0.f;
    float s_part[4] = {0.f, 0.f, 0.f, 0.f};

    for (int s = w; s < KVB / 16; s += 8) {     // warp owns k-steps s, s+8, ...
        const int nb = s * 16 + kp2;
        uint32_t aH[2][4], aL[2][4];
#pragma unroll
        for (int mt = 0; mt < 2; mt++) {
            float2 e00 = *(const float2*)(eR[mt * 2 + 0] + nb);
            float2 e10 = *(const float2*)(eR[mt * 2 + 1] + nb);
            float2 e01 = *(const float2*)(eR[mt * 2 + 0] + nb + 8);
            float2 e11 = *(const float2*)(eR[mt * 2 + 1] + nb + 8);
            e00.x = __expf(e00.x); e00.y = __expf(e00.y);
            e10.x = __expf(e10.x); e10.y = __expf(e10.y);
            e01.x = __expf(e01.x); e01.y = __expf(e01.y);
            e11.x = __expf(e11.x); e11.y = __expf(e11.y);
            s_part[mt * 2 + 0] += e00.x + e00.y + e01.x + e01.y;
            s_part[mt * 2 + 1] += e10.x + e10.y + e11.x + e11.y;
            cvt_hl2(e00, aH[mt][0], aL[mt][0]);   // a0: row, k lo
            cvt_hl2(e10, aH[mt][1], aL[mt][1]);   // a1: row+8, k lo
            cvt_hl2(e01, aH[mt][2], aL[mt][2]);   // a2: row, k hi
            cvt_hl2(e11, aH[mt][3], aL[mt][3]);   // a3: row+8, k hi
        }
#pragma unroll
        for (int nt = 0; nt < 8; nt++) {
            float2 v0 = *(const float2*)(vR[nt] + nb);
            float2 v1 = *(const float2*)(vR[nt] + nb + 8);
            uint32_t bh[2], bl[2];
            cvt_hl2(v0, bh[0], bl[0]);            // b0: k lo
            cvt_hl2(v1, bh[1], bl[1]);            // b1: k hi
#pragma unroll
            for (int mt = 0; mt < 2; mt++) {
                mma_bf16(d[mt][nt], aH[mt], bh);  // eh*vh
                mma_bf16(d[mt][nt], aL[mt], bh);  // el*vh
                mma_bf16(d[mt][nt], aH[mt], bl);  // eh*vl
            }
        }
    }

    // ---- s: xor-reduce over the 4-lane k-group (same r), then atomics ----
#pragma unroll
    for (int i = 0; i < 4; i++) {
        s_part[i] += __shfl_xor_sync(0xffffffffu, s_part[i], 1);
        s_part[i] += __shfl_xor_sync(0xffffffffu, s_part[i], 2);
    }
    if ((lane & 3) == 0) {
        float* spg = g_s + (b * NH + head) * DQK;
#pragma unroll
        for (int i = 0; i < 4; i++) {
            int row = (i >> 1) * 16 + (i & 1) * 8 + r;
            atomicAdd(&spg[row], s_part[i]);
        }
    }

    // ---- kv: cross-warp smem reduce, one atomic set per block ----
#pragma unroll
    for (int mt = 0; mt < 2; mt++)
#pragma unroll
        for (int nt = 0; nt < 8; nt++)
#pragma unroll
            for (int q = 0; q < 4; q++)
                red[w * 2048 + lane * 64 + (mt * 8 + nt) * 4 + q] = d[mt][nt][q];
    __syncthreads();

    float* kvp = g_kv + (size_t)((b * NH + head) * DQK) * DV;
#pragma unroll
    for (int j = 0; j < 8; j++) {
        const int e = j * 256 + tid;
        float ssum = 0.f;
#pragma unroll
        for (int ww = 0; ww < 8; ww++) ssum += red[ww * 2048 + e];
        const int l = e >> 6, idx = e & 63;
        const int f = idx >> 2, q = idx & 3;
        const int mt = f >> 3, nt = f & 7;
        const int dk = mt * 16 + (l >> 2) + (q >> 1) * 8;
        const int dv = nt * 8 + (l & 3) * 2 + (q & 1);
        atomicAdd(&kvp[dk * DV + dv], ssum);
    }
}

// ======================= K4: normalize kv ===========================
__global__ void k_kvnorm() {
    int i = blockIdx.x * 256 + threadIdx.x;
    if (i < Bb * NH * DQK * DV)
        g_kvn[i] = g_kv[i] / g_s[i / DV];
}

// ======================= K5: q softmax + matvec -> out =============
__global__ __launch_bounds__(256) void k_final(float* __restrict__ out) {
    __shared__ __align__(16) float kvs[NH][DQK][DV];
    const int b = blockIdx.y;
    const int n = blockIdx.x * 256 + threadIdx.x;
    for (int i = threadIdx.x; i < NH * DQK * DV; i += 256)
        ((float*)kvs)[i] = g_kvn[b * NH * DQK * DV + i];
    __syncthreads();

    const float* qp = g_qk + (size_t)b * Cc * Nn;
    float* op = out + (size_t)b * Cc * Nn;
    const float inv1e = 1.f / (1.f + EPSILON);

#pragma unroll 1
    for (int head = 0; head < NH; head++) {
        float e[DQK];
        float ssum = 0.f;
#pragma unroll
        for (int dk = 0; dk < DQK; dk++) {
            e[dk] = __expf(qp[(size_t)(head * DQK + dk) * Nn + n]);
            ssum += e[dk];
        }
        const float scale = inv1e / ssum;
        ull e2[DQK];
#pragma unroll
        for (int dk = 0; dk < DQK; dk++) {
            float s = e[dk] * scale;
            e2[dk] = pack2(s, s);
        }
#pragma unroll 1
        for (int dvg = 0; dvg < 8; dvg++) {
            ull a2[4] = {0ull, 0ull, 0ull, 0ull};
#pragma unroll
            for (int dk = 0; dk < DQK; dk++) {
                F4U2 ka, kb;
                ka.f4 = *(float4*)&kvs[head][dk][dvg * 8];
                kb.f4 = *(float4*)&kvs[head][dk][dvg * 8 + 4];
                fma2(a2[0], e2[dk], ka.u2[0]);
                fma2(a2[1], e2[dk], ka.u2[1]);
                fma2(a2[2], e2[dk], kb.u2[0]);
                fma2(a2[3], e2[dk], kb.u2[1]);
            }
            const int c = head * DV + dvg * 8;
#pragma unroll
            for (int p = 0; p < 4; p++) {
                float2 r = unpack2(a2[p]);
                op[(size_t)(c + 2 * p)     * Nn + n] = r.x;
                op[(size_t)(c + 2 * p + 1) * Nn + n] = r.y;
            }
        }
    }
}

// ======================= launch ===========================
extern "C" void kernel_launch(void* const* d_in, const int* in_sizes, int n_in,
                              void* d_out, int out_size) {
    const float* x  = (const float*)d_in[0];
    const float* Wq = (const float*)d_in[1];
    const float* Wk = (const float*)d_in[2];
    const float* Wv = (const float*)d_in[3];
    const float* bv = (const float*)d_in[4];
    float* out = (float*)d_out;

    cudaFuncSetAttribute(k_gemm_mma, cudaFuncAttributeMaxDynamicSharedMemorySize, GSM_TOT);
    cudaFuncSetAttribute(k_kv_mma, cudaFuncAttributeMaxDynamicSharedMemorySize, 65536);

    k_gemm_mma<<<dim3(Nn / 128, 2, Bb), 256, GSM_TOT>>>(x, Wq, Wk);
    k_conv_v<<<dim3(Hh / CONV_HT, Cc, Bb), 192>>>(x, Wv, bv);
    k_zero<<<64, 256>>>();
    k_kv_mma<<<dim3(Nn / KVB, NH, Bb), 256, 65536>>>();
    k_kvnorm<<<64, 256>>>();
    k_final<<<dim3(Nn / 256, Bb), 256>>>(out);
}

// round 13
// speedup vs baseline: 1.2452x; 1.0813x over previous
#include <cuda_runtime.h>
#include <cuda_bf16.h>
#include <cstdint>

#define Bb 2
#define Cc 256
#define Hh 48
#define Nn 110592        // 48*48*48
#define PLANE 2304       // 48*48
#define NH 4
#define DV 64
#define DQK 32
#define QKD 128
#define EPSILON 1e-6f

typedef unsigned long long ull;
typedef unsigned short ushort_t;

__device__ __forceinline__ void fma2(ull& d, ull a, ull b) {
    asm("fma.rn.f32x2 %0, %1, %2, %0;" : "+l"(d) : "l"(a), "l"(b));
}
__device__ __forceinline__ ull pack2(float lo, float hi) {
    ull r; asm("mov.b64 %0, {%1, %2};" : "=l"(r) : "f"(lo), "f"(hi)); return r;
}
__device__ __forceinline__ float2 unpack2(ull v) {
    float lo, hi; asm("mov.b64 {%0, %1}, %2;" : "=f"(lo), "=f"(hi) : "l"(v));
    return make_float2(lo, hi);
}
union F4U2 { float4 f4; ull u2[2]; };

// -------- scratch --------
__device__ __align__(16) float g_qk[(size_t)Bb * Cc * Nn];
__device__ __align__(16) float g_v[(size_t)Bb * Cc * Nn];
__device__ float g_kv[Bb * NH * DQK * DV];
__device__ float g_s[Bb * NH * DQK];
__device__ float g_kvn[Bb * NH * DQK * DV];

__device__ __forceinline__ uint32_t smem_u32(const void* p) {
    uint32_t a;
    asm("{ .reg .u64 t; cvta.to.shared.u64 t, %1; cvt.u32.u64 %0, t; }" : "=r"(a) : "l"(p));
    return a;
}

// ===================== mma.sync helpers (sm_80+ baseline PTX) ==============
__device__ __forceinline__ void ldsm4(uint32_t* r, uint32_t addr) {
    asm volatile("ldmatrix.sync.aligned.m8n8.x4.shared.b16 {%0,%1,%2,%3}, [%4];"
                 : "=r"(r[0]), "=r"(r[1]), "=r"(r[2]), "=r"(r[3]) : "r"(addr));
}
__device__ __forceinline__ void ldsm2t(uint32_t* r, uint32_t addr) {
    asm volatile("ldmatrix.sync.aligned.m8n8.x2.trans.shared.b16 {%0,%1}, [%2];"
                 : "=r"(r[0]), "=r"(r[1]) : "r"(addr));
}
__device__ __forceinline__ void mma_bf16(float* d, const uint32_t* a, const uint32_t* b) {
    asm volatile(
        "mma.sync.aligned.m16n8k16.row.col.f32.bf16.bf16.f32 "
        "{%0,%1,%2,%3}, {%4,%5,%6,%7}, {%8,%9}, {%0,%1,%2,%3};"
        : "+f"(d[0]), "+f"(d[1]), "+f"(d[2]), "+f"(d[3])
        : "r"(a[0]), "r"(a[1]), "r"(a[2]), "r"(a[3]), "r"(b[0]), "r"(b[1]));
}
__device__ __forceinline__ void cvt_hl4(float4 f, uint2& hi, uint2& lo) {
    __nv_bfloat16 hx = __float2bfloat16(f.x), hy = __float2bfloat16(f.y);
    __nv_bfloat16 hz = __float2bfloat16(f.z), hw = __float2bfloat16(f.w);
    __nv_bfloat16 lx = __float2bfloat16(f.x - __bfloat162float(hx));
    __nv_bfloat16 ly = __float2bfloat16(f.y - __bfloat162float(hy));
    __nv_bfloat16 lz = __float2bfloat16(f.z - __bfloat162float(hz));
    __nv_bfloat16 lw = __float2bfloat16(f.w - __bfloat162float(hw));
    hi.x = ((uint32_t)__bfloat16_as_ushort(hy) << 16) | __bfloat16_as_ushort(hx);
    hi.y = ((uint32_t)__bfloat16_as_ushort(hw) << 16) | __bfloat16_as_ushort(hz);
    lo.x = ((uint32_t)__bfloat16_as_ushort(ly) << 16) | __bfloat16_as_ushort(lx);
    lo.y = ((uint32_t)__bfloat16_as_ushort(lw) << 16) | __bfloat16_as_ushort(lz);
}
// float2 -> packed bf16x2 hi and lo (element 0 in low half)
__device__ __forceinline__ void cvt_hl2(float2 f, uint32_t& h, uint32_t& l) {
    __nv_bfloat16 hx = __float2bfloat16(f.x), hy = __float2bfloat16(f.y);
    __nv_bfloat16 lx = __float2bfloat16(f.x - __bfloat162float(hx));
    __nv_bfloat16 ly = __float2bfloat16(f.y - __bfloat162float(hy));
    h = ((uint32_t)__bfloat16_as_ushort(hy) << 16) | __bfloat16_as_ushort(hx);
    l = ((uint32_t)__bfloat16_as_ushort(ly) << 16) | __bfloat16_as_ushort(lx);
}

// ======================= K1: qk GEMM via mma.sync 3xBF16 ===================
#define GSM_AL 18432
#define GSM_BH 36864
#define GSM_BL 54272
#define GSM_TOT 71680

__global__ void __launch_bounds__(256, 2) k_gemm_mma(const float* __restrict__ x,
                                                     const float* __restrict__ Wq,
                                                     const float* __restrict__ Wk) {
    extern __shared__ __align__(16) char sm[];
    const int tid = threadIdx.x;
    const int lane = tid & 31, w = tid >> 5;
    const int n0 = blockIdx.x * 128;
    const int mh = blockIdx.y;
    const int b  = blockIdx.z;
    const float* Wsrc = mh ? Wk : Wq;
    const float* xb = x + (size_t)b * Cc * Nn;
    const uint32_t smb = smem_u32(sm);

    const int wm = (w & 1) * 64;
    const int wn = (w >> 1) * 32;

    const uint32_t aHi = smb + (wm + (lane & 15)) * 144 + (lane >> 4) * 16;
    const uint32_t aLo = aHi + GSM_AL;
    const uint32_t bHi = smb + GSM_BH + (lane & 15) * 272 + wn * 2;
    const uint32_t bLo = bHi + (GSM_BL - GSM_BH);

    float d[4][4][4];
#pragma unroll
    for (int mt = 0; mt < 4; mt++)
#pragma unroll
        for (int nt = 0; nt < 4; nt++)
#pragma unroll
            for (int r = 0; r < 4; r++) d[mt][nt][r] = 0.f;

    for (int kc = 0; kc < 4; kc++) {
        __syncthreads();
#pragma unroll
        for (int u = 0; u < 8; u++) {
            int i = u * 256 + tid;
            int row = i >> 4, g = i & 15;
            float4 f = *(const float4*)(Wsrc + (size_t)row * Cc + kc * 64 + g * 4);
            uint2 hi, lo; cvt_hl4(f, hi, lo);
            *(uint2*)(sm + row * 144 + g * 8) = hi;
            *(uint2*)(sm + GSM_AL + row * 144 + g * 8) = lo;
        }
#pragma unroll
        for (int u = 0; u < 8; u++) {
            int i = u * 256 + tid;
            int kr = i >> 5, ng = i & 31;
            float4 f = *(const float4*)(xb + (size_t)(kc * 64 + kr) * Nn + n0 + ng * 4);
            uint2 hi, lo; cvt_hl4(f, hi, lo);
            *(uint2*)(sm + GSM_BH + kr * 272 + ng * 8) = hi;
            *(uint2*)(sm + GSM_BL + kr * 272 + ng * 8) = lo;
        }
        __syncthreads();

#pragma unroll
        for (int s4 = 0; s4 < 4; s4++) {
            uint32_t ah[4][4], bh[4][2], t2[4][4];
#pragma unroll
            for (int mt = 0; mt < 4; mt++)
                ldsm4(ah[mt], aHi + mt * (16 * 144) + s4 * 32);
#pragma unroll
            for (int nt = 0; nt < 4; nt++)
                ldsm2t(bh[nt], bHi + s4 * (16 * 272) + nt * 16);
#pragma unroll
            for (int mt = 0; mt < 4; mt++)
#pragma unroll
                for (int nt = 0; nt < 4; nt++)
                    mma_bf16(d[mt][nt], ah[mt], bh[nt]);
#pragma unroll
            for (int nt = 0; nt < 4; nt++)
                ldsm2t(t2[nt], bLo + s4 * (16 * 272) + nt * 16);
#pragma unroll
            for (int mt = 0; mt < 4; mt++)
#pragma unroll
                for (int nt = 0; nt < 4; nt++)
                    mma_bf16(d[mt][nt], ah[mt], t2[nt]);
#pragma unroll
            for (int mt = 0; mt < 4; mt++)
                ldsm4(ah[mt], aLo + mt * (16 * 144) + s4 * 32);
#pragma unroll
            for (int mt = 0; mt < 4; mt++)
#pragma unroll
                for (int nt = 0; nt < 4; nt++)
                    mma_bf16(d[mt][nt], ah[mt], bh[nt]);
        }
    }

    float* outp = g_qk + (size_t)(b * Cc + mh * 128) * Nn + n0;
    const int r0 = lane >> 2, c0 = (lane & 3) * 2;
#pragma unroll
    for (int mt = 0; mt < 4; mt++) {
#pragma unroll
        for (int nt = 0; nt < 4; nt++) {
            float* p0 = outp + (size_t)(wm + mt * 16 + r0) * Nn + wn + nt * 8 + c0;
            *(float2*)p0 = make_float2(d[mt][nt][0], d[mt][nt][1]);
            float* p1 = p0 + (size_t)8 * Nn;
            *(float2*)p1 = make_float2(d[mt][nt][2], d[mt][nt][3]);
        }
    }
}

// ======================= K2: depthwise 3x3x3 conv (prefetch rolling) =======
#define CONV_HT 12
__global__ __launch_bounds__(192) void k_conv_v(const float* __restrict__ x,
                                                const float* __restrict__ Wv,
                                                const float* __restrict__ bv) {
    __shared__ float xs[4][48][48];   // rolling window, slot = (plane+4)&3
    const int h0 = blockIdx.x * CONV_HT, c = blockIdx.y, b = blockIdx.z;
    const float* xc = x + ((size_t)b * Cc + c) * Nn;
    const int tid = threadIdx.x;

    auto loadp = [&](int p) {
        float* dst = (float*)xs[(p + 4) & 3];
        if (p >= 0 && p < Hh) {
            for (int i = tid; i < 3 * PLANE; i += 192) { if (i < PLANE) dst[i] = xc[(size_t)p * PLANE + i]; }
        } else {
            for (int i = tid; i < PLANE; i += 192) dst[i] = 0.f;
        }
    };
    // simple full-plane load (12 elems/thread)
    auto loadp_full = [&](int p) {
        float* dst = (float*)xs[(p + 4) & 3];
        if (p >= 0 && p < Hh) {
#pragma unroll
            for (int j = 0; j < 12; j++) dst[tid + j * 192] = xc[(size_t)p * PLANE + tid + j * 192];
        } else {
#pragma unroll
            for (int j = 0; j < 12; j++) dst[tid + j * 192] = 0.f;
        }
    };

    float wv[27];
#pragma unroll
    for (int i = 0; i < 27; i++) wv[i] = Wv[c * 27 + i];
    const float bias = bv[c];

    loadp_full(h0 - 1); loadp_full(h0); loadp_full(h0 + 1);
    __syncthreads();

    const int w  = tid >> 2;
    const int d0 = (tid & 3) * 12;

    for (int hi = 0; hi < CONV_HT; hi++) {
        const int h = h0 + hi;
        const int pnext = h + 2;
        const bool doPre = (hi < CONV_HT - 1);

        // prefetch plane h+2 into registers BEFORE compute (hide LDG latency)
        float pr[12];
        if (doPre) {
            if (pnext < Hh) {
#pragma unroll
                for (int j = 0; j < 12; j++) pr[j] = xc[(size_t)pnext * PLANE + tid + j * 192];
            } else {
#pragma unroll
                for (int j = 0; j < 12; j++) pr[j] = 0.f;
            }
        }

        float o[12];
#pragma unroll
        for (int j = 0; j < 12; j++) o[j] = bias;

#pragma unroll
        for (int hh = 0; hh < 3; hh++) {
            const float* plane = (const float*)xs[(h - 1 + hh + 4) & 3];
#pragma unroll
            for (int ww = 0; ww < 3; ww++) {
                int wg = w + ww - 1;
                if (wg < 0 || wg >= 48) continue;
                const float* row = plane + wg * 48;
                const float w0 = wv[(hh * 3 + ww) * 3 + 0];
                const float w1 = wv[(hh * 3 + ww) * 3 + 1];
                const float w2 = wv[(hh * 3 + ww) * 3 + 2];
                float xm = (d0 > 0) ? row[d0 - 1] : 0.f;
                float x0 = row[d0];
#pragma unroll
                for (int j = 0; j < 12; j++) {
                    int d = d0 + j;
                    float xp = (d + 1 < 48) ? row[d + 1] : 0.f;
                    o[j] += w0 * xm + w1 * x0 + w2 * xp;
                    xm = x0; x0 = xp;
                }
            }
        }

        float* vp = g_v + ((size_t)b * Cc + c) * Nn + (size_t)h * PLANE + w * 48 + d0;
#pragma unroll
        for (int q = 0; q < 3; q++)
            *(float4*)(vp + q * 4) = make_float4(o[q*4], o[q*4+1], o[q*4+2], o[q*4+3]);

        // store prefetched plane into slot of h-2 (not read during this compute)
        if (doPre) {
            float* dst = (float*)xs[(pnext + 4) & 3];
#pragma unroll
            for (int j = 0; j < 12; j++) dst[tid + j * 192] = pr[j];
        }
        __syncthreads();
    }
}

// ======================= zero accumulators ===========================
__global__ void k_zero() {
    int i = blockIdx.x * 256 + threadIdx.x;
    if (i < Bb * NH * DQK * DV) g_kv[i] = 0.f;
    if (i < Bb * NH * DQK) g_s[i] = 0.f;
}

// ======================= K3: kv reduction, smem-free direct-fragment mma ===
#define KVB 2048     // n per block -> grid.x = 54 (432 blocks total)

__global__ __launch_bounds__(256) void k_kv_mma() {
    extern __shared__ __align__(16) float red[];   // 8 warps * 2048 floats
    const int b = blockIdx.z, head = blockIdx.y;
    const int n0 = blockIdx.x * KVB;
    const float* kp = g_qk + ((size_t)b * Cc + QKD + head * DQK) * Nn + n0;
    const float* vp = g_v  + ((size_t)b * Cc + head * DV) * Nn + n0;
    const int tid = threadIdx.x, lane = tid & 31, w = tid >> 5;
    const int r = lane >> 2, kp2 = (lane & 3) * 2;

    const float* eR[4] = {
        kp + (size_t)(r)      * Nn, kp + (size_t)(r + 8)  * Nn,
        kp + (size_t)(r + 16) * Nn, kp + (size_t)(r + 24) * Nn };
    const float* vR[8];
#pragma unroll
    for (int nt = 0; nt < 8; nt++) vR[nt] = vp + (size_t)(nt * 8 + r) * Nn;

    float d[2][8][4];
#pragma unroll
    for (int mt = 0; mt < 2; mt++)
#pragma unroll
        for (int nt = 0; nt < 8; nt++)
#pragma unroll
            for (int q = 0; q < 4; q++) d[mt][nt][q] = 0.f;
    float s_part[4] = {0.f, 0.f, 0.f, 0.f};

    for (int s = w; s < KVB / 16; s += 8) {
        const int nb = s * 16 + kp2;
        uint32_t aH[2][4], aL[2][4];
#pragma unroll
        for (int mt = 0; mt < 2; mt++) {
            float2 e00 = *(const float2*)(eR[mt * 2 + 0] + nb);
            float2 e10 = *(const float2*)(eR[mt * 2 + 1] + nb);
            float2 e01 = *(const float2*)(eR[mt * 2 + 0] + nb + 8);
            float2 e11 = *(const float2*)(eR[mt * 2 + 1] + nb + 8);
            e00.x = __expf(e00.x); e00.y = __expf(e00.y);
            e10.x = __expf(e10.x); e10.y = __expf(e10.y);
            e01.x = __expf(e01.x); e01.y = __expf(e01.y);
            e11.x = __expf(e11.x); e11.y = __expf(e11.y);
            s_part[mt * 2 + 0] += e00.x + e00.y + e01.x + e01.y;
            s_part[mt * 2 + 1] += e10.x + e10.y + e11.x + e11.y;
            cvt_hl2(e00, aH[mt][0], aL[mt][0]);
            cvt_hl2(e10, aH[mt][1], aL[mt][1]);
            cvt_hl2(e01, aH[mt][2], aL[mt][2]);
            cvt_hl2(e11, aH[mt][3], aL[mt][3]);
        }
#pragma unroll
        for (int nt = 0; nt < 8; nt++) {
            float2 v0 = *(const float2*)(vR[nt] + nb);
            float2 v1 = *(const float2*)(vR[nt] + nb + 8);
            uint32_t bh[2], bl[2];
            cvt_hl2(v0, bh[0], bl[0]);
            cvt_hl2(v1, bh[1], bl[1]);
#pragma unroll
            for (int mt = 0; mt < 2; mt++) {
                mma_bf16(d[mt][nt], aH[mt], bh);
                mma_bf16(d[mt][nt], aL[mt], bh);
                mma_bf16(d[mt][nt], aH[mt], bl);
            }
        }
    }

#pragma unroll
    for (int i = 0; i < 4; i++) {
        s_part[i] += __shfl_xor_sync(0xffffffffu, s_part[i], 1);
        s_part[i] += __shfl_xor_sync(0xffffffffu, s_part[i], 2);
    }
    if ((lane & 3) == 0) {
        float* spg = g_s + (b * NH + head) * DQK;
#pragma unroll
        for (int i = 0; i < 4; i++) {
            int row = (i >> 1) * 16 + (i & 1) * 8 + r;
            atomicAdd(&spg[row], s_part[i]);
        }
    }

#pragma unroll
    for (int mt = 0; mt < 2; mt++)
#pragma unroll
        for (int nt = 0; nt < 8; nt++)
#pragma unroll
            for (int q = 0; q < 4; q++)
                red[w * 2048 + lane * 64 + (mt * 8 + nt) * 4 + q] = d[mt][nt][q];
    __syncthreads();

    float* kvp = g_kv + (size_t)((b * NH + head) * DQK) * DV;
#pragma unroll
    for (int j = 0; j < 8; j++) {
        const int e = j * 256 + tid;
        float ssum = 0.f;
#pragma unroll
        for (int ww = 0; ww < 8; ww++) ssum += red[ww * 2048 + e];
        const int l = e >> 6, idx = e & 63;
        const int f = idx >> 2, q = idx & 3;
        const int mt = f >> 3, nt = f & 7;
        const int dk = mt * 16 + (l >> 2) + (q >> 1) * 8;
        const int dv = nt * 8 + (l & 3) * 2 + (q & 1);
        atomicAdd(&kvp[dk * DV + dv], ssum);
    }
}

// ======================= K4: normalize kv ===========================
__global__ void k_kvnorm() {
    int i = blockIdx.x * 256 + threadIdx.x;
    if (i < Bb * NH * DQK * DV)
        g_kvn[i] = g_kv[i] / g_s[i / DV];
}

// ======================= K5: q softmax + matvec -> out =============
__global__ __launch_bounds__(256) void k_final(float* __restrict__ out) {
    __shared__ __align__(16) float kvs[NH][DQK][DV];
    const int b = blockIdx.y;
    const int n = blockIdx.x * 256 + threadIdx.x;
    for (int i = threadIdx.x; i < NH * DQK * DV; i += 256)
        ((float*)kvs)[i] = g_kvn[b * NH * DQK * DV + i];
    __syncthreads();

    const float* qp = g_qk + (size_t)b * Cc * Nn;
    float* op = out + (size_t)b * Cc * Nn;
    const float inv1e = 1.f / (1.f + EPSILON);

#pragma unroll 1
    for (int head = 0; head < NH; head++) {
        float e[DQK];
        float ssum = 0.f;
#pragma unroll
        for (int dk = 0; dk < DQK; dk++) {
            e[dk] = __expf(qp[(size_t)(head * DQK + dk) * Nn + n]);
            ssum += e[dk];
        }
        const float scale = inv1e / ssum;
        ull e2[DQK];
#pragma unroll
        for (int dk = 0; dk < DQK; dk++) {
            float s = e[dk] * scale;
            e2[dk] = pack2(s, s);
        }
#pragma unroll 1
        for (int dvg = 0; dvg < 8; dvg++) {
            ull a2[4] = {0ull, 0ull, 0ull, 0ull};
#pragma unroll
            for (int dk = 0; dk < DQK; dk++) {
                F4U2 ka, kb;
                ka.f4 = *(float4*)&kvs[head][dk][dvg * 8];
                kb.f4 = *(float4*)&kvs[head][dk][dvg * 8 + 4];
                fma2(a2[0], e2[dk], ka.u2[0]);
                fma2(a2[1], e2[dk], ka.u2[1]);
                fma2(a2[2], e2[dk], kb.u2[0]);
                fma2(a2[3], e2[dk], kb.u2[1]);
            }
            const int c = head * DV + dvg * 8;
#pragma unroll
            for (int p = 0; p < 4; p++) {
                float2 r = unpack2(a2[p]);
                op[(size_t)(c + 2 * p)     * Nn + n] = r.x;
                op[(size_t)(c + 2 * p + 1) * Nn + n] = r.y;
            }
        }
    }
}

// ======================= launch ===========================
extern "C" void kernel_launch(void* const* d_in, const int* in_sizes, int n_in,
                              void* d_out, int out_size) {
    const float* x  = (const float*)d_in[0];
    const float* Wq = (const float*)d_in[1];
    const float* Wk = (const float*)d_in[2];
    const float* Wv = (const float*)d_in[3];
    const float* bv = (const float*)d_in[4];
    float* out = (float*)d_out;

    cudaFuncSetAttribute(k_gemm_mma, cudaFuncAttributeMaxDynamicSharedMemorySize, GSM_TOT);
    cudaFuncSetAttribute(k_kv_mma, cudaFuncAttributeMaxDynamicSharedMemorySize, 65536);

    k_gemm_mma<<<dim3(Nn / 128, 2, Bb), 256, GSM_TOT>>>(x, Wq, Wk);
    k_conv_v<<<dim3(Hh / CONV_HT, Cc, Bb), 192>>>(x, Wv, bv);
    k_zero<<<64, 256>>>();
    k_kv_mma<<<dim3(Nn / KVB, NH, Bb), 256, 65536>>>();
    k_kvnorm<<<64, 256>>>();
    k_final<<<dim3(Nn / 256, Bb), 256>>>(out);
}

// round 15
// speedup vs baseline: 1.2537x; 1.0068x over previous
#include <cuda_runtime.h>
#include <cuda_bf16.h>
#include <cstdint>

#define Bb 2
#define Cc 256
#define Hh 48
#define Nn 110592        // 48*48*48
#define PLANE 2304       // 48*48
#define NH 4
#define DV 64
#define DQK 32
#define QKD 128
#define EPSILON 1e-6f

typedef unsigned long long ull;
typedef unsigned short ushort_t;

__device__ __forceinline__ void fma2(ull& d, ull a, ull b) {
    asm("fma.rn.f32x2 %0, %1, %2, %0;" : "+l"(d) : "l"(a), "l"(b));
}
__device__ __forceinline__ ull pack2(float lo, float hi) {
    ull r; asm("mov.b64 %0, {%1, %2};" : "=l"(r) : "f"(lo), "f"(hi)); return r;
}
__device__ __forceinline__ float2 unpack2(ull v) {
    float lo, hi; asm("mov.b64 {%0, %1}, %2;" : "=f"(lo), "=f"(hi) : "l"(v));
    return make_float2(lo, hi);
}
union F4U2 { float4 f4; ull u2[2]; };

// -------- scratch --------
__device__ __align__(16) float g_qk[(size_t)Bb * Cc * Nn];
__device__ __align__(16) float g_v[(size_t)Bb * Cc * Nn];
__device__ float g_kv[Bb * NH * DQK * DV];
__device__ float g_s[Bb * NH * DQK];
__device__ float g_kvn[Bb * NH * DQK * DV];

__device__ __forceinline__ uint32_t smem_u32(const void* p) {
    uint32_t a;
    asm("{ .reg .u64 t; cvta.to.shared.u64 t, %1; cvt.u32.u64 %0, t; }" : "=r"(a) : "l"(p));
    return a;
}

// ===================== mma.sync helpers (sm_80+ baseline PTX) ==============
__device__ __forceinline__ void ldsm4(uint32_t* r, uint32_t addr) {
    asm volatile("ldmatrix.sync.aligned.m8n8.x4.shared.b16 {%0,%1,%2,%3}, [%4];"
                 : "=r"(r[0]), "=r"(r[1]), "=r"(r[2]), "=r"(r[3]) : "r"(addr));
}
__device__ __forceinline__ void ldsm2t(uint32_t* r, uint32_t addr) {
    asm volatile("ldmatrix.sync.aligned.m8n8.x2.trans.shared.b16 {%0,%1}, [%2];"
                 : "=r"(r[0]), "=r"(r[1]) : "r"(addr));
}
__device__ __forceinline__ void mma_bf16(float* d, const uint32_t* a, const uint32_t* b) {
    asm volatile(
        "mma.sync.aligned.m16n8k16.row.col.f32.bf16.bf16.f32 "
        "{%0,%1,%2,%3}, {%4,%5,%6,%7}, {%8,%9}, {%0,%1,%2,%3};"
        : "+f"(d[0]), "+f"(d[1]), "+f"(d[2]), "+f"(d[3])
        : "r"(a[0]), "r"(a[1]), "r"(a[2]), "r"(a[3]), "r"(b[0]), "r"(b[1]));
}
__device__ __forceinline__ void cvt_hl4(float4 f, uint2& hi, uint2& lo) {
    __nv_bfloat16 hx = __float2bfloat16(f.x), hy = __float2bfloat16(f.y);
    __nv_bfloat16 hz = __float2bfloat16(f.z), hw = __float2bfloat16(f.w);
    __nv_bfloat16 lx = __float2bfloat16(f.x - __bfloat162float(hx));
    __nv_bfloat16 ly = __float2bfloat16(f.y - __bfloat162float(hy));
    __nv_bfloat16 lz = __float2bfloat16(f.z - __bfloat162float(hz));
    __nv_bfloat16 lw = __float2bfloat16(f.w - __bfloat162float(hw));
    hi.x = ((uint32_t)__bfloat16_as_ushort(hy) << 16) | __bfloat16_as_ushort(hx);
    hi.y = ((uint32_t)__bfloat16_as_ushort(hw) << 16) | __bfloat16_as_ushort(hz);
    lo.x = ((uint32_t)__bfloat16_as_ushort(ly) << 16) | __bfloat16_as_ushort(lx);
    lo.y = ((uint32_t)__bfloat16_as_ushort(lw) << 16) | __bfloat16_as_ushort(lz);
}
// float2 -> packed bf16x2 hi and lo (element 0 in low half)
__device__ __forceinline__ void cvt_hl2(float2 f, uint32_t& h, uint32_t& l) {
    __nv_bfloat16 hx = __float2bfloat16(f.x), hy = __float2bfloat16(f.y);
    __nv_bfloat16 lx = __float2bfloat16(f.x - __bfloat162float(hx));
    __nv_bfloat16 ly = __float2bfloat16(f.y - __bfloat162float(hy));
    h = ((uint32_t)__bfloat16_as_ushort(hy) << 16) | __bfloat16_as_ushort(hx);
    l = ((uint32_t)__bfloat16_as_ushort(ly) << 16) | __bfloat16_as_ushort(lx);
}

// ======================= K1: fused qk GEMM (M=256, N=64 per CTA) ===========
// A = [Wq;Wk] stacked (256 x 256); each CTA owns one 64-wide n-slice so x is
// read exactly ONCE chip-wide. 8 warps = 4m x 2n, warp tile 64x32 (unchanged).
// smem: AH@0 (256x144), AL@36864, BH@73728 (64x144), BL@82944; total 92160.
#define GQ_AL 36864
#define GQ_BH 73728
#define GQ_BL 82944
#define GQ_TOT 92160

__global__ void __launch_bounds__(256, 2) k_gemm_mma(const float* __restrict__ x,
                                                     const float* __restrict__ Wq,
                                                     const float* __restrict__ Wk) {
    extern __shared__ __align__(16) char sm[];
    const int tid = threadIdx.x;
    const int lane = tid & 31, w = tid >> 5;
    const int n0 = blockIdx.x * 64;
    const int b  = blockIdx.y;
    const float* xb = x + (size_t)b * Cc * Nn;
    const uint32_t smb = smem_u32(sm);

    const int wm = (w & 3) * 64;       // warp M offset (0..192)
    const int wn = (w >> 2) * 32;      // warp N offset (0 or 32)

    const uint32_t aHi = smb + (wm + (lane & 15)) * 144 + (lane >> 4) * 16;
    const uint32_t aLo = aHi + GQ_AL;
    const uint32_t bHi = smb + GQ_BH + (lane & 15) * 144 + wn * 2;
    const uint32_t bLo = bHi + (GQ_BL - GQ_BH);

    float d[4][4][4];
#pragma unroll
    for (int mt = 0; mt < 4; mt++)
#pragma unroll
        for (int nt = 0; nt < 4; nt++)
#pragma unroll
            for (int r = 0; r < 4; r++) d[mt][nt][r] = 0.f;

    for (int kc = 0; kc < 4; kc++) {
        __syncthreads();
        // A: 256 rows x 64 k -> 4096 float4, 16 per thread
#pragma unroll
        for (int u = 0; u < 16; u++) {
            int i = u * 256 + tid;
            int row = i >> 4, g = i & 15;
            const float* wr = (row < 128) ? (Wq + (size_t)row * Cc)
                                          : (Wk + (size_t)(row - 128) * Cc);
            float4 f = *(const float4*)(wr + kc * 64 + g * 4);
            uint2 hi, lo; cvt_hl4(f, hi, lo);
            *(uint2*)(sm + row * 144 + g * 8) = hi;
            *(uint2*)(sm + GQ_AL + row * 144 + g * 8) = lo;
        }
        // B: 64 krows x 64 n -> 1024 float4, 4 per thread
#pragma unroll
        for (int u = 0; u < 4; u++) {
            int i = u * 256 + tid;
            int kr = i >> 4, ng = i & 15;
            float4 f = *(const float4*)(xb + (size_t)(kc * 64 + kr) * Nn + n0 + ng * 4);
            uint2 hi, lo; cvt_hl4(f, hi, lo);
            *(uint2*)(sm + GQ_BH + kr * 144 + ng * 8) = hi;
            *(uint2*)(sm + GQ_BL + kr * 144 + ng * 8) = lo;
        }
        __syncthreads();

#pragma unroll
        for (int s4 = 0; s4 < 4; s4++) {
            uint32_t ah[4][4], bh[4][2], t2[4][4];
#pragma unroll
            for (int mt = 0; mt < 4; mt++)
                ldsm4(ah[mt], aHi + mt * (16 * 144) + s4 * 32);
#pragma unroll
            for (int nt = 0; nt < 4; nt++)
                ldsm2t(bh[nt], bHi + s4 * (16 * 144) + nt * 16);
#pragma unroll
            for (int mt = 0; mt < 4; mt++)
#pragma unroll
                for (int nt = 0; nt < 4; nt++)
                    mma_bf16(d[mt][nt], ah[mt], bh[nt]);
#pragma unroll
            for (int nt = 0; nt < 4; nt++)
                ldsm2t(t2[nt], bLo + s4 * (16 * 144) + nt * 16);
#pragma unroll
            for (int mt = 0; mt < 4; mt++)
#pragma unroll
                for (int nt = 0; nt < 4; nt++)
                    mma_bf16(d[mt][nt], ah[mt], t2[nt]);
#pragma unroll
            for (int mt = 0; mt < 4; mt++)
                ldsm4(ah[mt], aLo + mt * (16 * 144) + s4 * 32);
#pragma unroll
            for (int mt = 0; mt < 4; mt++)
#pragma unroll
                for (int nt = 0; nt < 4; nt++)
                    mma_bf16(d[mt][nt], ah[mt], bh[nt]);
        }
    }

    float* outp = g_qk + (size_t)b * Cc * Nn + n0;
    const int r0 = lane >> 2, c0 = (lane & 3) * 2;
#pragma unroll
    for (int mt = 0; mt < 4; mt++) {
#pragma unroll
        for (int nt = 0; nt < 4; nt++) {
            float* p0 = outp + (size_t)(wm + mt * 16 + r0) * Nn + wn + nt * 8 + c0;
            *(float2*)p0 = make_float2(d[mt][nt][0], d[mt][nt][1]);
            float* p1 = p0 + (size_t)8 * Nn;
            *(float2*)p1 = make_float2(d[mt][nt][2], d[mt][nt][3]);
        }
    }
}

// ======================= K2: depthwise 3x3x3 conv (prefetch rolling) =======
#define CONV_HT 12
__global__ __launch_bounds__(192) void k_conv_v(const float* __restrict__ x,
                                                const float* __restrict__ Wv,
                                                const float* __restrict__ bv) {
    __shared__ float xs[4][48][48];   // rolling window, slot = (plane+4)&3
    const int h0 = blockIdx.x * CONV_HT, c = blockIdx.y, b = blockIdx.z;
    const float* xc = x + ((size_t)b * Cc + c) * Nn;
    const int tid = threadIdx.x;

    auto loadp_full = [&](int p) {
        float* dst = (float*)xs[(p + 4) & 3];
        if (p >= 0 && p < Hh) {
#pragma unroll
            for (int j = 0; j < 12; j++) dst[tid + j * 192] = xc[(size_t)p * PLANE + tid + j * 192];
        } else {
#pragma unroll
            for (int j = 0; j < 12; j++) dst[tid + j * 192] = 0.f;
        }
    };

    float wv[27];
#pragma unroll
    for (int i = 0; i < 27; i++) wv[i] = Wv[c * 27 + i];
    const float bias = bv[c];

    loadp_full(h0 - 1); loadp_full(h0); loadp_full(h0 + 1);
    __syncthreads();

    const int w  = tid >> 2;
    const int d0 = (tid & 3) * 12;

    for (int hi = 0; hi < CONV_HT; hi++) {
        const int h = h0 + hi;
        const int pnext = h + 2;
        const bool doPre = (hi < CONV_HT - 1);

        float pr[12];
        if (doPre) {
            if (pnext < Hh) {
#pragma unroll
                for (int j = 0; j < 12; j++) pr[j] = xc[(size_t)pnext * PLANE + tid + j * 192];
            } else {
#pragma unroll
                for (int j = 0; j < 12; j++) pr[j] = 0.f;
            }
        }

        float o[12];
#pragma unroll
        for (int j = 0; j < 12; j++) o[j] = bias;

#pragma unroll
        for (int hh = 0; hh < 3; hh++) {
            const float* plane = (const float*)xs[(h - 1 + hh + 4) & 3];
#pragma unroll
            for (int ww = 0; ww < 3; ww++) {
                int wg = w + ww - 1;
                if (wg < 0 || wg >= 48) continue;
                const float* row = plane + wg * 48;
                const float w0 = wv[(hh * 3 + ww) * 3 + 0];
                const float w1 = wv[(hh * 3 + ww) * 3 + 1];
                const float w2 = wv[(hh * 3 + ww) * 3 + 2];
                float xm = (d0 > 0) ? row[d0 - 1] : 0.f;
                float x0 = row[d0];
#pragma unroll
                for (int j = 0; j < 12; j++) {
                    int d = d0 + j;
                    float xp = (d + 1 < 48) ? row[d + 1] : 0.f;
                    o[j] += w0 * xm + w1 * x0 + w2 * xp;
                    xm = x0; x0 = xp;
                }
            }
        }

        float* vp = g_v + ((size_t)b * Cc + c) * Nn + (size_t)h * PLANE + w * 48 + d0;
#pragma unroll
        for (int q = 0; q < 3; q++)
            *(float4*)(vp + q * 4) = make_float4(o[q*4], o[q*4+1], o[q*4+2], o[q*4+3]);

        if (doPre) {
            float* dst = (float*)xs[(pnext + 4) & 3];
#pragma unroll
            for (int j = 0; j < 12; j++) dst[tid + j * 192] = pr[j];
        }
        __syncthreads();
    }
}

// ======================= zero accumulators ===========================
__global__ void k_zero() {
    int i = blockIdx.x * 256 + threadIdx.x;
    if (i < Bb * NH * DQK * DV) g_kv[i] = 0.f;
    if (i < Bb * NH * DQK) g_s[i] = 0.f;
}

// ======================= K3: kv reduction, smem-free direct-fragment mma ===
#define KVB 2048     // n per block -> 432 blocks total

__global__ __launch_bounds__(256) void k_kv_mma() {
    extern __shared__ __align__(16) float red[];   // 8 warps * 2048 floats
    const int b = blockIdx.z, head = blockIdx.y;
    const int n0 = blockIdx.x * KVB;
    const float* kp = g_qk + ((size_t)b * Cc + QKD + head * DQK) * Nn + n0;
    const float* vp = g_v  + ((size_t)b * Cc + head * DV) * Nn + n0;
    const int tid = threadIdx.x, lane = tid & 31, w = tid >> 5;
    const int r = lane >> 2, kp2 = (lane & 3) * 2;

    const float* eR[4] = {
        kp + (size_t)(r)      * Nn, kp + (size_t)(r + 8)  * Nn,
        kp + (size_t)(r + 16) * Nn, kp + (size_t)(r + 24) * Nn };
    const float* vR[8];
#pragma unroll
    for (int nt = 0; nt < 8; nt++) vR[nt] = vp + (size_t)(nt * 8 + r) * Nn;

    float d[2][8][4];
#pragma unroll
    for (int mt = 0; mt < 2; mt++)
#pragma unroll
        for (int nt = 0; nt < 8; nt++)
#pragma unroll
            for (int q = 0; q < 4; q++) d[mt][nt][q] = 0.f;
    float s_part[4] = {0.f, 0.f, 0.f, 0.f};

    for (int s = w; s < KVB / 16; s += 8) {
        const int nb = s * 16 + kp2;
        uint32_t aH[2][4], aL[2][4];
#pragma unroll
        for (int mt = 0; mt < 2; mt++) {
            float2 e00 = *(const float2*)(eR[mt * 2 + 0] + nb);
            float2 e10 = *(const float2*)(eR[mt * 2 + 1] + nb);
            float2 e01 = *(const float2*)(eR[mt * 2 + 0] + nb + 8);
            float2 e11 = *(const float2*)(eR[mt * 2 + 1] + nb + 8);
            e00.x = __expf(e00.x); e00.y = __expf(e00.y);
            e10.x = __expf(e10.x); e10.y = __expf(e10.y);
            e01.x = __expf(e01.x); e01.y = __expf(e01.y);
            e11.x = __expf(e11.x); e11.y = __expf(e11.y);
            s_part[mt * 2 + 0] += e00.x + e00.y + e01.x + e01.y;
            s_part[mt * 2 + 1] += e10.x + e10.y + e11.x + e11.y;
            cvt_hl2(e00, aH[mt][0], aL[mt][0]);
            cvt_hl2(e10, aH[mt][1], aL[mt][1]);
            cvt_hl2(e01, aH[mt][2], aL[mt][2]);
            cvt_hl2(e11, aH[mt][3], aL[mt][3]);
        }
#pragma unroll
        for (int nt = 0; nt < 8; nt++) {
            float2 v0 = *(const float2*)(vR[nt] + nb);
            float2 v1 = *(const float2*)(vR[nt] + nb + 8);
            uint32_t bh[2], bl[2];
            cvt_hl2(v0, bh[0], bl[0]);
            cvt_hl2(v1, bh[1], bl[1]);
#pragma unroll
            for (int mt = 0; mt < 2; mt++) {
                mma_bf16(d[mt][nt], aH[mt], bh);
                mma_bf16(d[mt][nt], aL[mt], bh);
                mma_bf16(d[mt][nt], aH[mt], bl);
            }
        }
    }

#pragma unroll
    for (int i = 0; i < 4; i++) {
        s_part[i] += __shfl_xor_sync(0xffffffffu, s_part[i], 1);
        s_part[i] += __shfl_xor_sync(0xffffffffu, s_part[i], 2);
    }
    if ((lane & 3) == 0) {
        float* spg = g_s + (b * NH + head) * DQK;
#pragma unroll
        for (int i = 0; i < 4; i++) {
            int row = (i >> 1) * 16 + (i & 1) * 8 + r;
            atomicAdd(&spg[row], s_part[i]);
        }
    }

#pragma unroll
    for (int mt = 0; mt < 2; mt++)
#pragma unroll
        for (int nt = 0; nt < 8; nt++)
#pragma unroll
            for (int q = 0; q < 4; q++)
                red[w * 2048 + lane * 64 + (mt * 8 + nt) * 4 + q] = d[mt][nt][q];
    __syncthreads();

    float* kvp = g_kv + (size_t)((b * NH + head) * DQK) * DV;
#pragma unroll
    for (int j = 0; j < 8; j++) {
        const int e = j * 256 + tid;
        float ssum = 0.f;
#pragma unroll
        for (int ww = 0; ww < 8; ww++) ssum += red[ww * 2048 + e];
        const int l = e >> 6, idx = e & 63;
        const int f = idx >> 2, q = idx & 3;
        const int mt = f >> 3, nt = f & 7;
        const int dk = mt * 16 + (l >> 2) + (q >> 1) * 8;
        const int dv = nt * 8 + (l & 3) * 2 + (q & 1);
        atomicAdd(&kvp[dk * DV + dv], ssum);
    }
}

// ======================= K4: normalize kv ===========================
__global__ void k_kvnorm() {
    int i = blockIdx.x * 256 + threadIdx.x;
    if (i < Bb * NH * DQK * DV)
        g_kvn[i] = g_kv[i] / g_s[i / DV];
}

// ======================= K5: q softmax + matvec -> out =============
__global__ __launch_bounds__(256) void k_final(float* __restrict__ out) {
    __shared__ __align__(16) float kvs[NH][DQK][DV];
    const int b = blockIdx.y;
    const int n = blockIdx.x * 256 + threadIdx.x;
    for (int i = threadIdx.x; i < NH * DQK * DV; i += 256)
        ((float*)kvs)[i] = g_kvn[b * NH * DQK * DV + i];
    __syncthreads();

    const float* qp = g_qk + (size_t)b * Cc * Nn;
    float* op = out + (size_t)b * Cc * Nn;
    const float inv1e = 1.f / (1.f + EPSILON);

#pragma unroll 1
    for (int head = 0; head < NH; head++) {
        float e[DQK];
        float ssum = 0.f;
#pragma unroll
        for (int dk = 0; dk < DQK; dk++) {
            e[dk] = __expf(qp[(size_t)(head * DQK + dk) * Nn + n]);
            ssum += e[dk];
        }
        const float scale = inv1e / ssum;
        ull e2[DQK];
#pragma unroll
        for (int dk = 0; dk < DQK; dk++) {
            float s = e[dk] * scale;
            e2[dk] = pack2(s, s);
        }
#pragma unroll 1
        for (int dvg = 0; dvg < 8; dvg++) {
            ull a2[4] = {0ull, 0ull, 0ull, 0ull};
#pragma unroll
            for (int dk = 0; dk < DQK; dk++) {
                F4U2 ka, kb;
                ka.f4 = *(float4*)&kvs[head][dk][dvg * 8];
                kb.f4 = *(float4*)&kvs[head][dk][dvg * 8 + 4];
                fma2(a2[0], e2[dk], ka.u2[0]);
                fma2(a2[1], e2[dk], ka.u2[1]);
                fma2(a2[2], e2[dk], kb.u2[0]);
                fma2(a2[3], e2[dk], kb.u2[1]);
            }
            const int c = head * DV + dvg * 8;
#pragma unroll
            for (int p = 0; p < 4; p++) {
                float2 r = unpack2(a2[p]);
                op[(size_t)(c + 2 * p)     * Nn + n] = r.x;
                op[(size_t)(c + 2 * p + 1) * Nn + n] = r.y;
            }
        }
    }
}

// ======================= launch ===========================
extern "C" void kernel_launch(void* const* d_in, const int* in_sizes, int n_in,
                              void* d_out, int out_size) {
    const float* x  = (const float*)d_in[0];
    const float* Wq = (const float*)d_in[1];
    const float* Wk = (const float*)d_in[2];
    const float* Wv = (const float*)d_in[3];
    const float* bv = (const float*)d_in[4];
    float* out = (float*)d_out;

    cudaFuncSetAttribute(k_gemm_mma, cudaFuncAttributeMaxDynamicSharedMemorySize, GQ_TOT);
    cudaFuncSetAttribute(k_kv_mma, cudaFuncAttributeMaxDynamicSharedMemorySize, 65536);

    k_gemm_mma<<<dim3(Nn / 64, Bb), 256, GQ_TOT>>>(x, Wq, Wk);
    k_conv_v<<<dim3(Hh / CONV_HT, Cc, Bb), 192>>>(x, Wv, bv);
    k_zero<<<64, 256>>>();
    k_kv_mma<<<dim3(Nn / KVB, NH, Bb), 256, 65536>>>();
    k_kvnorm<<<64, 256>>>();
    k_final<<<dim3(Nn / 256, Bb), 256>>>(out);
}

// round 17
// speedup vs baseline: 1.3850x; 1.1047x over previous
#include <cuda_runtime.h>
#include <cuda_bf16.h>
#include <cuda_fp16.h>
#include <cstdint>

#define Bb 2
#define Cc 256
#define Hh 48
#define Nn 110592        // 48*48*48
#define PLANE 2304       // 48*48
#define NH 4
#define DV 64
#define DQK 32
#define QKD 128
#define EPSILON 1e-6f

typedef unsigned long long ull;

__device__ __forceinline__ void fma2(ull& d, ull a, ull b) {
    asm("fma.rn.f32x2 %0, %1, %2, %0;" : "+l"(d) : "l"(a), "l"(b));
}
__device__ __forceinline__ ull pack2(float lo, float hi) {
    ull r; asm("mov.b64 %0, {%1, %2};" : "=l"(r) : "f"(lo), "f"(hi)); return r;
}
__device__ __forceinline__ float2 unpack2(ull v) {
    float lo, hi; asm("mov.b64 {%0, %1}, %2;" : "=f"(lo), "=f"(hi) : "l"(v));
    return make_float2(lo, hi);
}
union F4U2 { float4 f4; ull u2[2]; };

// -------- scratch --------
__device__ __align__(16) float  g_qk[(size_t)Bb * QKD * Nn];   // q logits fp32
__device__ __align__(16) __half g_kh[(size_t)Bb * QKD * Nn];   // k logits fp16
__device__ __align__(16) __half g_v [(size_t)Bb * Cc  * Nn];   // conv out fp16
__device__ float g_kv[Bb * NH * DQK * DV];
__device__ float g_s[Bb * NH * DQK];
__device__ float g_kvn[Bb * NH * DQK * DV];

__device__ __forceinline__ uint32_t smem_u32(const void* p) {
    uint32_t a;
    asm("{ .reg .u64 t; cvta.to.shared.u64 t, %1; cvt.u32.u64 %0, t; }" : "=r"(a) : "l"(p));
    return a;
}

// ===================== mma.sync helpers (sm_80+ baseline PTX) ==============
__device__ __forceinline__ void ldsm4(uint32_t* r, uint32_t addr) {
    asm volatile("ldmatrix.sync.aligned.m8n8.x4.shared.b16 {%0,%1,%2,%3}, [%4];"
                 : "=r"(r[0]), "=r"(r[1]), "=r"(r[2]), "=r"(r[3]) : "r"(addr));
}
__device__ __forceinline__ void ldsm2t(uint32_t* r, uint32_t addr) {
    asm volatile("ldmatrix.sync.aligned.m8n8.x2.trans.shared.b16 {%0,%1}, [%2];"
                 : "=r"(r[0]), "=r"(r[1]) : "r"(addr));
}
__device__ __forceinline__ void mma_bf16(float* d, const uint32_t* a, const uint32_t* b) {
    asm volatile(
        "mma.sync.aligned.m16n8k16.row.col.f32.bf16.bf16.f32 "
        "{%0,%1,%2,%3}, {%4,%5,%6,%7}, {%8,%9}, {%0,%1,%2,%3};"
        : "+f"(d[0]), "+f"(d[1]), "+f"(d[2]), "+f"(d[3])
        : "r"(a[0]), "r"(a[1]), "r"(a[2]), "r"(a[3]), "r"(b[0]), "r"(b[1]));
}
__device__ __forceinline__ void cvt_hl4(float4 f, uint2& hi, uint2& lo) {
    __nv_bfloat16 hx = __float2bfloat16(f.x), hy = __float2bfloat16(f.y);
    __nv_bfloat16 hz = __float2bfloat16(f.z), hw = __float2bfloat16(f.w);
    __nv_bfloat16 lx = __float2bfloat16(f.x - __bfloat162float(hx));
    __nv_bfloat16 ly = __float2bfloat16(f.y - __bfloat162float(hy));
    __nv_bfloat16 lz = __float2bfloat16(f.z - __bfloat162float(hz));
    __nv_bfloat16 lw = __float2bfloat16(f.w - __bfloat162float(hw));
    hi.x = ((uint32_t)__bfloat16_as_ushort(hy) << 16) | __bfloat16_as_ushort(hx);
    hi.y = ((uint32_t)__bfloat16_as_ushort(hw) << 16) | __bfloat16_as_ushort(hz);
    lo.x = ((uint32_t)__bfloat16_as_ushort(ly) << 16) | __bfloat16_as_ushort(lx);
    lo.y = ((uint32_t)__bfloat16_as_ushort(lw) << 16) | __bfloat16_as_ushort(lz);
}
// float2 -> packed bf16x2 hi and lo (element 0 in low half)
__device__ __forceinline__ void cvt_hl2(float2 f, uint32_t& h, uint32_t& l) {
    __nv_bfloat16 hx = __float2bfloat16(f.x), hy = __float2bfloat16(f.y);
    __nv_bfloat16 lx = __float2bfloat16(f.x - __bfloat162float(hx));
    __nv_bfloat16 ly = __float2bfloat16(f.y - __bfloat162float(hy));
    h = ((uint32_t)__bfloat16_as_ushort(hy) << 16) | __bfloat16_as_ushort(hx);
    l = ((uint32_t)__bfloat16_as_ushort(ly) << 16) | __bfloat16_as_ushort(lx);
}

// ======================= K1: fused qk GEMM (M=256, N=64 per CTA) ===========
// q half (rows 0..127) -> g_qk fp32; k half (rows 128..255) -> g_kh fp16.
#define GQ_AL 36864
#define GQ_BH 73728
#define GQ_BL 82944
#define GQ_TOT 92160

__global__ void __launch_bounds__(256, 2) k_gemm_mma(const float* __restrict__ x,
                                                     const float* __restrict__ Wq,
                                                     const float* __restrict__ Wk) {
    extern __shared__ __align__(16) char sm[];
    const int tid = threadIdx.x;
    const int lane = tid & 31, w = tid >> 5;
    const int n0 = blockIdx.x * 64;
    const int b  = blockIdx.y;
    const float* xb = x + (size_t)b * Cc * Nn;
    const uint32_t smb = smem_u32(sm);

    const int wm = (w & 3) * 64;       // warp M offset (0..192)
    const int wn = (w >> 2) * 32;      // warp N offset (0 or 32)

    const uint32_t aHi = smb + (wm + (lane & 15)) * 144 + (lane >> 4) * 16;
    const uint32_t aLo = aHi + GQ_AL;
    const uint32_t bHi = smb + GQ_BH + (lane & 15) * 144 + wn * 2;
    const uint32_t bLo = bHi + (GQ_BL - GQ_BH);

    float d[4][4][4];
#pragma unroll
    for (int mt = 0; mt < 4; mt++)
#pragma unroll
        for (int nt = 0; nt < 4; nt++)
#pragma unroll
            for (int r = 0; r < 4; r++) d[mt][nt][r] = 0.f;

    for (int kc = 0; kc < 4; kc++) {
        __syncthreads();
#pragma unroll
        for (int u = 0; u < 16; u++) {
            int i = u * 256 + tid;
            int row = i >> 4, g = i & 15;
            const float* wr = (row < 128) ? (Wq + (size_t)row * Cc)
                                          : (Wk + (size_t)(row - 128) * Cc);
            float4 f = *(const float4*)(wr + kc * 64 + g * 4);
            uint2 hi, lo; cvt_hl4(f, hi, lo);
            *(uint2*)(sm + row * 144 + g * 8) = hi;
            *(uint2*)(sm + GQ_AL + row * 144 + g * 8) = lo;
        }
#pragma unroll
        for (int u = 0; u < 4; u++) {
            int i = u * 256 + tid;
            int kr = i >> 4, ng = i & 15;
            float4 f = *(const float4*)(xb + (size_t)(kc * 64 + kr) * Nn + n0 + ng * 4);
            uint2 hi, lo; cvt_hl4(f, hi, lo);
            *(uint2*)(sm + GQ_BH + kr * 144 + ng * 8) = hi;
            *(uint2*)(sm + GQ_BL + kr * 144 + ng * 8) = lo;
        }
        __syncthreads();

#pragma unroll
        for (int s4 = 0; s4 < 4; s4++) {
            uint32_t ah[4][4], bh[4][2], t2[4][4];
#pragma unroll
            for (int mt = 0; mt < 4; mt++)
                ldsm4(ah[mt], aHi + mt * (16 * 144) + s4 * 32);
#pragma unroll
            for (int nt = 0; nt < 4; nt++)
                ldsm2t(bh[nt], bHi + s4 * (16 * 144) + nt * 16);
#pragma unroll
            for (int mt = 0; mt < 4; mt++)
#pragma unroll
                for (int nt = 0; nt < 4; nt++)
                    mma_bf16(d[mt][nt], ah[mt], bh[nt]);
#pragma unroll
            for (int nt = 0; nt < 4; nt++)
                ldsm2t(t2[nt], bLo + s4 * (16 * 144) + nt * 16);
#pragma unroll
            for (int mt = 0; mt < 4; mt++)
#pragma unroll
                for (int nt = 0; nt < 4; nt++)
                    mma_bf16(d[mt][nt], ah[mt], t2[nt]);
#pragma unroll
            for (int mt = 0; mt < 4; mt++)
                ldsm4(ah[mt], aLo + mt * (16 * 144) + s4 * 32);
#pragma unroll
            for (int mt = 0; mt < 4; mt++)
#pragma unroll
                for (int nt = 0; nt < 4; nt++)
                    mma_bf16(d[mt][nt], ah[mt], bh[nt]);
        }
    }

    const int r0 = lane >> 2, c0 = (lane & 3) * 2;
    if (wm < 128) {
        // q half -> fp32
        float* outp = g_qk + (size_t)b * QKD * Nn + n0;
#pragma unroll
        for (int mt = 0; mt < 4; mt++) {
#pragma unroll
            for (int nt = 0; nt < 4; nt++) {
                float* p0 = outp + (size_t)(wm + mt * 16 + r0) * Nn + wn + nt * 8 + c0;
                *(float2*)p0 = make_float2(d[mt][nt][0], d[mt][nt][1]);
                float* p1 = p0 + (size_t)8 * Nn;
                *(float2*)p1 = make_float2(d[mt][nt][2], d[mt][nt][3]);
            }
        }
    } else {
        // k half -> fp16
        __half* outp = g_kh + (size_t)b * QKD * Nn + n0;
        const int km = wm - 128;
#pragma unroll
        for (int mt = 0; mt < 4; mt++) {
#pragma unroll
            for (int nt = 0; nt < 4; nt++) {
                __half* p0 = outp + (size_t)(km + mt * 16 + r0) * Nn + wn + nt * 8 + c0;
                *(__half2*)p0 = __floats2half2_rn(d[mt][nt][0], d[mt][nt][1]);
                __half* p1 = p0 + (size_t)8 * Nn;
                *(__half2*)p1 = __floats2half2_rn(d[mt][nt][2], d[mt][nt][3]);
            }
        }
    }
}

// ======================= K2: depthwise 3x3x3 conv (prefetch rolling) =======
#define CONV_HT 12
__global__ __launch_bounds__(192) void k_conv_v(const float* __restrict__ x,
                                                const float* __restrict__ Wv,
                                                const float* __restrict__ bv) {
    __shared__ float xs[4][48][48];   // rolling window, slot = (plane+4)&3
    const int h0 = blockIdx.x * CONV_HT, c = blockIdx.y, b = blockIdx.z;
    const float* xc = x + ((size_t)b * Cc + c) * Nn;
    const int tid = threadIdx.x;

    auto loadp_full = [&](int p) {
        float* dst = (float*)xs[(p + 4) & 3];
        if (p >= 0 && p < Hh) {
#pragma unroll
            for (int j = 0; j < 12; j++) dst[tid + j * 192] = xc[(size_t)p * PLANE + tid + j * 192];
        } else {
#pragma unroll
            for (int j = 0; j < 12; j++) dst[tid + j * 192] = 0.f;
        }
    };

    float wv[27];
#pragma unroll
    for (int i = 0; i < 27; i++) wv[i] = Wv[c * 27 + i];
    const float bias = bv[c];

    loadp_full(h0 - 1); loadp_full(h0); loadp_full(h0 + 1);
    __syncthreads();

    const int w  = tid >> 2;
    const int d0 = (tid & 3) * 12;

    for (int hi = 0; hi < CONV_HT; hi++) {
        const int h = h0 + hi;
        const int pnext = h + 2;
        const bool doPre = (hi < CONV_HT - 1);

        float pr[12];
        if (doPre) {
            if (pnext < Hh) {
#pragma unroll
                for (int j = 0; j < 12; j++) pr[j] = xc[(size_t)pnext * PLANE + tid + j * 192];
            } else {
#pragma unroll
                for (int j = 0; j < 12; j++) pr[j] = 0.f;
            }
        }

        float o[12];
#pragma unroll
        for (int j = 0; j < 12; j++) o[j] = bias;

#pragma unroll
        for (int hh = 0; hh < 3; hh++) {
            const float* plane = (const float*)xs[(h - 1 + hh + 4) & 3];
#pragma unroll
            for (int ww = 0; ww < 3; ww++) {
                int wg = w + ww - 1;
                if (wg < 0 || wg >= 48) continue;
                const float* row = plane + wg * 48;
                const float w0 = wv[(hh * 3 + ww) * 3 + 0];
                const float w1 = wv[(hh * 3 + ww) * 3 + 1];
                const float w2 = wv[(hh * 3 + ww) * 3 + 2];
                float xm = (d0 > 0) ? row[d0 - 1] : 0.f;
                float x0 = row[d0];
#pragma unroll
                for (int j = 0; j < 12; j++) {
                    int d = d0 + j;
                    float xp = (d + 1 < 48) ? row[d + 1] : 0.f;
                    o[j] += w0 * xm + w1 * x0 + w2 * xp;
                    xm = x0; x0 = xp;
                }
            }
        }

        __half* vp = g_v + ((size_t)b * Cc + c) * Nn + (size_t)h * PLANE + w * 48 + d0;
#pragma unroll
        for (int q = 0; q < 6; q++)
            *(__half2*)(vp + q * 2) = __floats2half2_rn(o[q * 2], o[q * 2 + 1]);

        if (doPre) {
            float* dst = (float*)xs[(pnext + 4) & 3];
#pragma unroll
            for (int j = 0; j < 12; j++) dst[tid + j * 192] = pr[j];
        }
        __syncthreads();
    }
}

// ======================= zero accumulators ===========================
__global__ void k_zero() {
    int i = blockIdx.x * 256 + threadIdx.x;
    if (i < Bb * NH * DQK * DV) g_kv[i] = 0.f;
    if (i < Bb * NH * DQK) g_s[i] = 0.f;
}

// ======================= K3: kv reduction, smem-free direct-fragment mma ===
#define KVB 2048     // n per block -> 432 blocks total

__global__ __launch_bounds__(256) void k_kv_mma() {
    extern __shared__ __align__(16) float red[];   // 8 warps * 2048 floats
    const int b = blockIdx.z, head = blockIdx.y;
    const int n0 = blockIdx.x * KVB;
    const __half* kp = g_kh + ((size_t)b * QKD + head * DQK) * Nn + n0;
    const __half* vp = g_v  + ((size_t)b * Cc  + head * DV)  * Nn + n0;
    const int tid = threadIdx.x, lane = tid & 31, w = tid >> 5;
    const int r = lane >> 2, kp2 = (lane & 3) * 2;

    const __half* eR[4] = {
        kp + (size_t)(r)      * Nn, kp + (size_t)(r + 8)  * Nn,
        kp + (size_t)(r + 16) * Nn, kp + (size_t)(r + 24) * Nn };
    const __half* vR[8];
#pragma unroll
    for (int nt = 0; nt < 8; nt++) vR[nt] = vp + (size_t)(nt * 8 + r) * Nn;

    float d[2][8][4];
#pragma unroll
    for (int mt = 0; mt < 2; mt++)
#pragma unroll
        for (int nt = 0; nt < 8; nt++)
#pragma unroll
            for (int q = 0; q < 4; q++) d[mt][nt][q] = 0.f;
    float s_part[4] = {0.f, 0.f, 0.f, 0.f};

    for (int s = w; s < KVB / 16; s += 8) {
        const int nb = s * 16 + kp2;
        uint32_t aH[2][4], aL[2][4];
#pragma unroll
        for (int mt = 0; mt < 2; mt++) {
            float2 e00 = __half22float2(*(const __half2*)(eR[mt * 2 + 0] + nb));
            float2 e10 = __half22float2(*(const __half2*)(eR[mt * 2 + 1] + nb));
            float2 e01 = __half22float2(*(const __half2*)(eR[mt * 2 + 0] + nb + 8));
            float2 e11 = __half22float2(*(const __half2*)(eR[mt * 2 + 1] + nb + 8));
            e00.x = __expf(e00.x); e00.y = __expf(e00.y);
            e10.x = __expf(e10.x); e10.y = __expf(e10.y);
            e01.x = __expf(e01.x); e01.y = __expf(e01.y);
            e11.x = __expf(e11.x); e11.y = __expf(e11.y);
            s_part[mt * 2 + 0] += e00.x + e00.y + e01.x + e01.y;
            s_part[mt * 2 + 1] += e10.x + e10.y + e11.x + e11.y;
            cvt_hl2(e00, aH[mt][0], aL[mt][0]);
            cvt_hl2(e10, aH[mt][1], aL[mt][1]);
            cvt_hl2(e01, aH[mt][2], aL[mt][2]);
            cvt_hl2(e11, aH[mt][3], aL[mt][3]);
        }
#pragma unroll
        for (int nt = 0; nt < 8; nt++) {
            float2 v0 = __half22float2(*(const __half2*)(vR[nt] + nb));
            float2 v1 = __half22float2(*(const __half2*)(vR[nt] + nb + 8));
            uint32_t bh[2], bl[2];
            cvt_hl2(v0, bh[0], bl[0]);
            cvt_hl2(v1, bh[1], bl[1]);
#pragma unroll
            for (int mt = 0; mt < 2; mt++) {
                mma_bf16(d[mt][nt], aH[mt], bh);
                mma_bf16(d[mt][nt], aL[mt], bh);
                mma_bf16(d[mt][nt], aH[mt], bl);
            }
        }
    }

#pragma unroll
    for (int i = 0; i < 4; i++) {
        s_part[i] += __shfl_xor_sync(0xffffffffu, s_part[i], 1);
        s_part[i] += __shfl_xor_sync(0xffffffffu, s_part[i], 2);
    }
    if ((lane & 3) == 0) {
        float* spg = g_s + (b * NH + head) * DQK;
#pragma unroll
        for (int i = 0; i < 4; i++) {
            int row = (i >> 1) * 16 + (i & 1) * 8 + r;
            atomicAdd(&spg[row], s_part[i]);
        }
    }

#pragma unroll
    for (int mt = 0; mt < 2; mt++)
#pragma unroll
        for (int nt = 0; nt < 8; nt++)
#pragma unroll
            for (int q = 0; q < 4; q++)
                red[w * 2048 + lane * 64 + (mt * 8 + nt) * 4 + q] = d[mt][nt][q];
    __syncthreads();

    float* kvp = g_kv + (size_t)((b * NH + head) * DQK) * DV;
#pragma unroll
    for (int j = 0; j < 8; j++) {
        const int e = j * 256 + tid;
        float ssum = 0.f;
#pragma unroll
        for (int ww = 0; ww < 8; ww++) ssum += red[ww * 2048 + e];
        const int l = e >> 6, idx = e & 63;
        const int f = idx >> 2, q = idx & 3;
        const int mt = f >> 3, nt = f & 7;
        const int dk = mt * 16 + (l >> 2) + (q >> 1) * 8;
        const int dv = nt * 8 + (l & 3) * 2 + (q & 1);
        atomicAdd(&kvp[dk * DV + dv], ssum);
    }
}

// ======================= K4: normalize kv ===========================
__global__ void k_kvnorm() {
    int i = blockIdx.x * 256 + threadIdx.x;
    if (i < Bb * NH * DQK * DV)
        g_kvn[i] = g_kv[i] / g_s[i / DV];
}

// ======================= K5: q softmax + matvec -> out =============
__global__ __launch_bounds__(256) void k_final(float* __restrict__ out) {
    __shared__ __align__(16) float kvs[NH][DQK][DV];
    const int b = blockIdx.y;
    const int n = blockIdx.x * 256 + threadIdx.x;
    for (int i = threadIdx.x; i < NH * DQK * DV; i += 256)
        ((float*)kvs)[i] = g_kvn[b * NH * DQK * DV + i];
    __syncthreads();

    const float* qp = g_qk + (size_t)b * QKD * Nn;
    float* op = out + (size_t)b * Cc * Nn;
    const float inv1e = 1.f / (1.f + EPSILON);

#pragma unroll 1
    for (int head = 0; head < NH; head++) {
        float e[DQK];
        float ssum = 0.f;
#pragma unroll
        for (int dk = 0; dk < DQK; dk++) {
            e[dk] = __expf(qp[(size_t)(head * DQK + dk) * Nn + n]);
            ssum += e[dk];
        }
        const float scale = inv1e / ssum;
        ull e2[DQK];
#pragma unroll
        for (int dk = 0; dk < DQK; dk++) {
            float s = e[dk] * scale;
            e2[dk] = pack2(s, s);
        }
#pragma unroll 1
        for (int dvg = 0; dvg < 8; dvg++) {
            ull a2[4] = {0ull, 0ull, 0ull, 0ull};
#pragma unroll
            for (int dk = 0; dk < DQK; dk++) {
                F4U2 ka, kb;
                ka.f4 = *(float4*)&kvs[head][dk][dvg * 8];
                kb.f4 = *(float4*)&kvs[head][dk][dvg * 8 + 4];
                fma2(a2[0], e2[dk], ka.u2[0]);
                fma2(a2[1], e2[dk], ka.u2[1]);
                fma2(a2[2], e2[dk], kb.u2[0]);
                fma2(a2[3], e2[dk], kb.u2[1]);
            }
            const int c = head * DV + dvg * 8;
#pragma unroll
            for (int p = 0; p < 4; p++) {
                float2 r = unpack2(a2[p]);
                op[(size_t)(c + 2 * p)     * Nn + n] = r.x;
                op[(size_t)(c + 2 * p + 1) * Nn + n] = r.y;
            }
        }
    }
}

// ======================= launch ===========================
extern "C" void kernel_launch(void* const* d_in, const int* in_sizes, int n_in,
                              void* d_out, int out_size) {
    const float* x  = (const float*)d_in[0];
    const float* Wq = (const float*)d_in[1];
    const float* Wk = (const float*)d_in[2];
    const float* Wv = (const float*)d_in[3];
    const float* bv = (const float*)d_in[4];
    float* out = (float*)d_out;

    cudaFuncSetAttribute(k_gemm_mma, cudaFuncAttributeMaxDynamicSharedMemorySize, GQ_TOT);
    cudaFuncSetAttribute(k_kv_mma, cudaFuncAttributeMaxDynamicSharedMemorySize, 65536);

    k_gemm_mma<<<dim3(Nn / 64, Bb), 256, GQ_TOT>>>(x, Wq, Wk);
    k_conv_v<<<dim3(Hh / CONV_HT, Cc, Bb), 192>>>(x, Wv, bv);
    k_zero<<<64, 256>>>();
    k_kv_mma<<<dim3(Nn / KVB, NH, Bb), 256, 65536>>>();
    k_kvnorm<<<64, 256>>>();
    k_final<<<dim3(Nn / 256, Bb), 256>>>(out);
}